// round 6
// baseline (speedup 1.0000x reference)
#include <cuda_runtime.h>
#include <cuda_bf16.h>
#include <math.h>
#include <stdint.h>

#define NN 100000
#define EE 1600000
#define CC 128
#define SCAN_BLOCKS ((NN + 255) / 256)   // 391

// ---------------------------------------------------------------------------
// Scratch (allocation-free rule: __device__ globals)
// ---------------------------------------------------------------------------
__device__ float g_h[(size_t)NN * CC];    // fp32 h (resid + LN)
__device__ float g_nb[(size_t)NN * CC];   // fp32 neighbor (gathered by k_aggr)

// Pre-split bf16 activation pairs (GEMM A operands)
__device__ __nv_bfloat16 g_uh[(size_t)NN * CC],  g_ul[(size_t)NN * CC];   // lift-hidden / gate1-out
__device__ __nv_bfloat16 g_hh[(size_t)NN * CC],  g_hl[(size_t)NN * CC];   // h
__device__ __nv_bfloat16 g_sfh[(size_t)NN * CC], g_sfl[(size_t)NN * CC];  // self_f
__device__ __nv_bfloat16 g_agh[(size_t)NN * CC], g_agl[(size_t)NN * CC];  // aggr

// CSR scratch
__device__ int   g_cnt[NN];
__device__ int   g_rowstart[NN + 1];
__device__ int   g_cursor[NN];
__device__ int   g_bsum[SCAN_BLOCKS];
__device__ int   g_boff[SCAN_BLOCKS];
__device__ int   g_ecol[EE];
__device__ float g_eval[EE];

// Pre-converted bf16 weight tiles (hi/lo split), layout [slot][n][k]
#define WSLOTS 11
__device__ __nv_bfloat16 g_wbh[(size_t)WSLOTS * 16384];
__device__ __nv_bfloat16 g_wbl[(size_t)WSLOTS * 16384];

__device__ __forceinline__ float gelu_f(float v) {
    return 0.5f * v * (1.0f + erff(v * 0.7071067811865475f));
}
__device__ __forceinline__ void split_bf16(float v, __nv_bfloat16& hi, __nv_bfloat16& lo) {
    hi = __float2bfloat16(v);
    lo = __float2bfloat16(v - __bfloat162float(hi));
}

// ---------------------------------------------------------------------------
// mma.sync / cp.async helpers
// ---------------------------------------------------------------------------
__device__ __forceinline__ void ldsm_x4(uint32_t* r, uint32_t addr) {
    asm volatile("ldmatrix.sync.aligned.m8n8.x4.shared.b16 {%0,%1,%2,%3}, [%4];"
                 : "=r"(r[0]), "=r"(r[1]), "=r"(r[2]), "=r"(r[3]) : "r"(addr));
}
__device__ __forceinline__ void mma16816(float* d, const uint32_t* a, const uint32_t* b) {
    asm volatile(
        "mma.sync.aligned.m16n8k16.row.col.f32.bf16.bf16.f32 "
        "{%0,%1,%2,%3}, {%4,%5,%6,%7}, {%8,%9}, {%0,%1,%2,%3};"
        : "+f"(d[0]), "+f"(d[1]), "+f"(d[2]), "+f"(d[3])
        : "r"(a[0]), "r"(a[1]), "r"(a[2]), "r"(a[3]), "r"(b[0]), "r"(b[1]));
}
__device__ __forceinline__ void cp16(uint32_t dst, const void* src, int srcsize) {
    asm volatile("cp.async.cg.shared.global [%0], [%1], 16, %2;"
                 :: "r"(dst), "l"(src), "r"(srcsize) : "memory");
}
__device__ __forceinline__ void cp_commit() {
    asm volatile("cp.async.commit_group;" ::: "memory");
}
__device__ __forceinline__ void cp_wait_all() {
    asm volatile("cp.async.wait_group 0;" ::: "memory");
}

// ---------------------------------------------------------------------------
// Smem layout: A (single) + B (double buffered). 208896 bytes total.
// ---------------------------------------------------------------------------
#define ROWB 272
#define TILEB (128 * ROWB)          // 34816
#define SM_AH 0
#define SM_AL TILEB
#define SM_B0 (2 * TILEB)           // BH0, BL0
#define SM_B1 (4 * TILEB)           // BH1, BL1
#define SM_TOTAL (6 * TILEB)        // 208896

// 3-term bf16-split MMA over a staged 128-K chunk.
__device__ __forceinline__ void mma_chunk(float acc[2][8][4], uint32_t aH,
                                          uint32_t aL, uint32_t bH, uint32_t bL) {
#pragma unroll
    for (int ks = 0; ks < 8; ks++) {
        uint32_t ah[2][4], al[2][4], bh[4][4], bl[4][4];
        ldsm_x4(ah[0], aH + ks * 32);
        ldsm_x4(ah[1], aH + ks * 32 + 16 * ROWB);
        ldsm_x4(al[0], aL + ks * 32);
        ldsm_x4(al[1], aL + ks * 32 + 16 * ROWB);
#pragma unroll
        for (int np = 0; np < 4; np++) {
            ldsm_x4(bh[np], bH + ks * 32 + np * 16 * ROWB);
            ldsm_x4(bl[np], bL + ks * 32 + np * 16 * ROWB);
        }
#pragma unroll
        for (int mi = 0; mi < 2; mi++)
#pragma unroll
            for (int nt = 0; nt < 8; nt++) {
                uint32_t bbh[2] = { bh[nt >> 1][(nt & 1) * 2], bh[nt >> 1][(nt & 1) * 2 + 1] };
                uint32_t bbl[2] = { bl[nt >> 1][(nt & 1) * 2], bl[nt >> 1][(nt & 1) * 2 + 1] };
                mma16816(acc[mi][nt], ah[mi], bbh);
                mma16816(acc[mi][nt], ah[mi], bbl);
                mma16816(acc[mi][nt], al[mi], bbh);
            }
    }
}

// Stage pre-split A (pure async copies, zfill OOB rows).
__device__ __forceinline__ void stage_A(uint32_t sb, const __nv_bfloat16* __restrict__ Ah,
                                        const __nv_bfloat16* __restrict__ Al,
                                        int m0, int tid) {
#pragma unroll
    for (int i = 0; i < 8; i++) {
        int ci = tid + i * 256;
        int row = ci >> 4, ch = ci & 15;
        int gm = m0 + row;
        int ss = (gm < NN) ? 16 : 0;
        int gms = (gm < NN) ? gm : (NN - 1);
        uint32_t off = (uint32_t)(row * ROWB + ch * 16);
        cp16(sb + SM_AH + off, Ah + (size_t)gms * 128 + ch * 8, ss);
        cp16(sb + SM_AL + off, Al + (size_t)gms * 128 + ch * 8, ss);
    }
}
// Stage weight tile pair into buffer at base `sm_b`.
__device__ __forceinline__ void stage_B(uint32_t sb, uint32_t sm_b,
                                        const __nv_bfloat16* __restrict__ Bh,
                                        const __nv_bfloat16* __restrict__ Bl, int tid) {
#pragma unroll
    for (int i = 0; i < 8; i++) {
        int ci = tid + i * 256;
        int row = ci >> 4, ch = ci & 15;
        uint32_t off = (uint32_t)(row * ROWB + ch * 16);
        cp16(sb + sm_b + off, Bh + ci * 8, 16);
        cp16(sb + sm_b + TILEB + off, Bl + ci * 8, 16);
    }
}

// Epilogue: acc (+bias, act, +resid) -> fp32 and/or split bf16 outputs.
template <int GELU, int RESID, int WF32, int WSPLIT>
__device__ __forceinline__ void epilogue(float acc[2][8][4], const float* __restrict__ bias,
                                         const float* __restrict__ R,
                                         float* __restrict__ OutF,
                                         __nv_bfloat16* __restrict__ OutH,
                                         __nv_bfloat16* __restrict__ OutL,
                                         int m0, int warp_m, int warp_n, int lane) {
    float b0[8], b1[8];
#pragma unroll
    for (int nt = 0; nt < 8; nt++) {
        int col = warp_n * 64 + nt * 8 + (lane & 3) * 2;
        b0[nt] = __ldg(bias + col);
        b1[nt] = __ldg(bias + col + 1);
    }
#pragma unroll
    for (int mi = 0; mi < 2; mi++) {
        int r0 = m0 + warp_m * 32 + mi * 16 + (lane >> 2);
#pragma unroll
        for (int half = 0; half < 2; half++) {
            int r = r0 + half * 8;
            if (r >= NN) continue;
            const float* rrow = RESID ? (R + (size_t)r * 128) : nullptr;
#pragma unroll
            for (int nt = 0; nt < 8; nt++) {
                int col = warp_n * 64 + nt * 8 + (lane & 3) * 2;
                float x0 = acc[mi][nt][half * 2 + 0] + b0[nt];
                float x1 = acc[mi][nt][half * 2 + 1] + b1[nt];
                if (GELU) { x0 = gelu_f(x0); x1 = gelu_f(x1); }
                if (RESID) {
                    float2 rr = *(const float2*)(rrow + col);
                    x0 += rr.x; x1 += rr.y;
                }
                if (WF32)
                    *(float2*)(OutF + (size_t)r * 128 + col) = make_float2(x0, x1);
                if (WSPLIT) {
                    __nv_bfloat16 h0, l0, h1, l1;
                    split_bf16(x0, h0, l0);
                    split_bf16(x1, h1, l1);
                    *(__nv_bfloat162*)(OutH + (size_t)r * 128 + col) =
                        __nv_bfloat162(h0, h1);
                    *(__nv_bfloat162*)(OutL + (size_t)r * 128 + col) =
                        __nv_bfloat162(l0, l1);
                }
            }
        }
    }
}

#define ACC_ZERO(acc)                                   \
    _Pragma("unroll")                                   \
    for (int mi = 0; mi < 2; mi++)                      \
        _Pragma("unroll")                               \
        for (int nt = 0; nt < 8; nt++)                  \
            _Pragma("unroll")                           \
            for (int e = 0; e < 4; e++) acc[mi][nt][e] = 0.0f;

// ---------------------------------------------------------------------------
// Generic GEMM (pre-split A). kchunks in {1,2}; B double-buffer prefetch.
// ---------------------------------------------------------------------------
template <int GELU, int RESID, int WF32, int WSPLIT>
__global__ void __launch_bounds__(256, 1) gemm_mma(
    const __nv_bfloat16* __restrict__ A0h, const __nv_bfloat16* __restrict__ A0l,
    const __nv_bfloat16* __restrict__ A1h, const __nv_bfloat16* __restrict__ A1l,
    const __nv_bfloat16* __restrict__ Bh, const __nv_bfloat16* __restrict__ Bl,
    const float* __restrict__ bias, const float* __restrict__ R,
    float* __restrict__ OutF, __nv_bfloat16* __restrict__ OutH,
    __nv_bfloat16* __restrict__ OutL, int kchunks) {
    extern __shared__ __align__(16) char smem[];
    const uint32_t sb = (uint32_t)__cvta_generic_to_shared(smem);
    const int tid = threadIdx.x;
    const int lane = tid & 31;
    const int warp_m = (tid >> 5) >> 1;
    const int warp_n = (tid >> 5) & 1;
    const int m0 = blockIdx.x * 128;

    const uint32_t a_lane = (uint32_t)(((lane & 7) + ((lane >> 3) & 1) * 8) * ROWB +
                                       (lane >> 4) * 16);
    const uint32_t b_lane = (uint32_t)(((lane & 7) + ((lane >> 4) & 1) * 8) * ROWB +
                                       ((lane >> 3) & 1) * 16);
    const uint32_t aH = sb + SM_AH + (uint32_t)(warp_m * 32 * ROWB) + a_lane;
    const uint32_t aL = sb + SM_AL + (uint32_t)(warp_m * 32 * ROWB) + a_lane;
    const uint32_t bOff = (uint32_t)(warp_n * 64 * ROWB) + b_lane;

    float acc[2][8][4];
    ACC_ZERO(acc);

    stage_A(sb, A0h, A0l, m0, tid);
    stage_B(sb, SM_B0, Bh, Bl, tid);
    cp_commit();
    cp_wait_all();
    __syncthreads();

    if (kchunks == 2) {
        // prefetch chunk-1 weights during chunk-0 MMA
        stage_B(sb, SM_B1, Bh + 16384, Bl + 16384, tid);
        cp_commit();
    }
    mma_chunk(acc, aH, aL, sb + SM_B0 + bOff, sb + SM_B0 + TILEB + bOff);

    if (kchunks == 2) {
        __syncthreads();                    // everyone done reading A chunk 0
        stage_A(sb, A1h, A1l, m0, tid);
        cp_commit();
        cp_wait_all();
        __syncthreads();
        mma_chunk(acc, aH, aL, sb + SM_B1 + bOff, sb + SM_B1 + TILEB + bOff);
    }
    epilogue<GELU, RESID, WF32, WSPLIT>(acc, bias, R, OutF, OutH, OutL,
                                        m0, warp_m, warp_n, lane);
}

// ---------------------------------------------------------------------------
// Fused neighbor+self GEMM: stage A (= h split) once, two weight sets.
// ---------------------------------------------------------------------------
__global__ void __launch_bounds__(256, 1) gemm_ns(
    const __nv_bfloat16* __restrict__ Ah, const __nv_bfloat16* __restrict__ Al,
    const __nv_bfloat16* __restrict__ Bnh, const __nv_bfloat16* __restrict__ Bnl,
    const float* __restrict__ bn, float* __restrict__ OutN,
    const __nv_bfloat16* __restrict__ Bsh, const __nv_bfloat16* __restrict__ Bsl,
    const float* __restrict__ bs, __nv_bfloat16* __restrict__ OutSh,
    __nv_bfloat16* __restrict__ OutSl) {
    extern __shared__ __align__(16) char smem[];
    const uint32_t sb = (uint32_t)__cvta_generic_to_shared(smem);
    const int tid = threadIdx.x;
    const int lane = tid & 31;
    const int warp_m = (tid >> 5) >> 1;
    const int warp_n = (tid >> 5) & 1;
    const int m0 = blockIdx.x * 128;

    const uint32_t a_lane = (uint32_t)(((lane & 7) + ((lane >> 3) & 1) * 8) * ROWB +
                                       (lane >> 4) * 16);
    const uint32_t b_lane = (uint32_t)(((lane & 7) + ((lane >> 4) & 1) * 8) * ROWB +
                                       ((lane >> 3) & 1) * 16);
    const uint32_t aH = sb + SM_AH + (uint32_t)(warp_m * 32 * ROWB) + a_lane;
    const uint32_t aL = sb + SM_AL + (uint32_t)(warp_m * 32 * ROWB) + a_lane;
    const uint32_t bOff = (uint32_t)(warp_n * 64 * ROWB) + b_lane;

    stage_A(sb, Ah, Al, m0, tid);
    stage_B(sb, SM_B0, Bnh, Bnl, tid);
    cp_commit();
    cp_wait_all();
    __syncthreads();

    // prefetch self weights during neighbor MMA
    stage_B(sb, SM_B1, Bsh, Bsl, tid);
    cp_commit();

    float acc[2][8][4];
    ACC_ZERO(acc);
    mma_chunk(acc, aH, aL, sb + SM_B0 + bOff, sb + SM_B0 + TILEB + bOff);
    epilogue<0, 0, 1, 0>(acc, bn, nullptr, OutN, nullptr, nullptr,
                         m0, warp_m, warp_n, lane);

    cp_wait_all();
    __syncthreads();

    ACC_ZERO(acc);
    mma_chunk(acc, aH, aL, sb + SM_B1 + bOff, sb + SM_B1 + TILEB + bOff);
    epilogue<0, 0, 0, 1>(acc, bs, nullptr, nullptr, OutSh, OutSl,
                         m0, warp_m, warp_n, lane);
}

// ---------------------------------------------------------------------------
// Weight conversion: fp32 W[K,N] -> bf16 hi/lo B[N,K]
// ---------------------------------------------------------------------------
__global__ void wconv_kernel(const float* __restrict__ lw2,
                             const float* __restrict__ sw,
                             const float* __restrict__ nw,
                             const float* __restrict__ gw1,
                             const float* __restrict__ gw2) {
    int idx = blockIdx.x * blockDim.x + threadIdx.x;
    if (idx >= WSLOTS * 16384) return;
    int slot = idx >> 14;
    int within = idx & 16383;
    int n = within >> 7;
    int k = within & 127;
    const float* src;
    if (slot == 0) {
        src = lw2 + k * 128 + n;
    } else {
        int l = (slot - 1) / 5, j = (slot - 1) % 5;
        if (j == 0)      src = nw  + (size_t)l * 16384 + k * 128 + n;
        else if (j == 1) src = sw  + (size_t)l * 16384 + k * 128 + n;
        else if (j == 2) src = gw1 + (size_t)l * 32768 + k * 128 + n;
        else if (j == 3) src = gw1 + (size_t)l * 32768 + 16384 + k * 128 + n;
        else             src = gw2 + (size_t)l * 16384 + k * 128 + n;
    }
    __nv_bfloat16 hi, lo;
    split_bf16(*src, hi, lo);
    g_wbh[idx] = hi;
    g_wbl[idx] = lo;
}

// ---------------------------------------------------------------------------
// CSR build: count -> scan -> fill
// ---------------------------------------------------------------------------
__global__ void k_zero_cnt() {
    int i = blockIdx.x * blockDim.x + threadIdx.x;
    if (i < NN) g_cnt[i] = 0;
}
__global__ void k_count(const int* __restrict__ ei) {
    int e = blockIdx.x * blockDim.x + threadIdx.x;
    if (e < EE) atomicAdd(&g_cnt[ei[e]], 1);
}
__global__ void k_blocksum() {
    __shared__ int sh[256];
    int i = blockIdx.x * 256 + threadIdx.x;
    int v = (i < NN) ? g_cnt[i] : 0;
    sh[threadIdx.x] = v;
    __syncthreads();
    for (int s = 128; s; s >>= 1) {
        if (threadIdx.x < s) sh[threadIdx.x] += sh[threadIdx.x + s];
        __syncthreads();
    }
    if (threadIdx.x == 0) g_bsum[blockIdx.x] = sh[0];
}
__global__ void k_scan_bsum() {
    __shared__ int sh[512];
    int t = threadIdx.x;
    sh[t] = (t < SCAN_BLOCKS) ? g_bsum[t] : 0;
    __syncthreads();
    for (int off = 1; off < 512; off <<= 1) {
        int v = (t >= off) ? sh[t - off] : 0;
        __syncthreads();
        sh[t] += v;
        __syncthreads();
    }
    if (t < SCAN_BLOCKS) g_boff[t] = sh[t] - g_bsum[t];
}
__global__ void k_rowstart() {
    __shared__ int sh[256];
    int i = blockIdx.x * 256 + threadIdx.x;
    int v = (i < NN) ? g_cnt[i] : 0;
    sh[threadIdx.x] = v;
    __syncthreads();
    for (int off = 1; off < 256; off <<= 1) {
        int u = (threadIdx.x >= off) ? sh[threadIdx.x - off] : 0;
        __syncthreads();
        sh[threadIdx.x] += u;
        __syncthreads();
    }
    if (i < NN) {
        int excl = sh[threadIdx.x] - v + g_boff[blockIdx.x];
        g_rowstart[i] = excl;
        g_cursor[i] = excl;
        if (i == NN - 1) g_rowstart[NN] = excl + v;
    }
}
__global__ void k_fill(const int* __restrict__ ei, const float* __restrict__ ev) {
    int e = blockIdx.x * blockDim.x + threadIdx.x;
    if (e >= EE) return;
    int row = ei[e];
    int pos = atomicAdd(&g_cursor[row], 1);
    g_ecol[pos] = ei[EE + e];
    g_eval[pos] = ev[e];
}

// ---------------------------------------------------------------------------
// Pull aggregation: one warp per row; writes split bf16 directly.
// ---------------------------------------------------------------------------
__global__ void k_aggr() {
    int r = blockIdx.x * 8 + (threadIdx.x >> 5);
    if (r >= NN) return;
    int lane = threadIdx.x & 31;
    int s = g_rowstart[r];
    int e = g_rowstart[r + 1];
    float acc[4] = {0.f, 0.f, 0.f, 0.f};
    for (int j = s; j < e; j++) {
        int c = __ldg(&g_ecol[j]);
        float v = __ldg(&g_eval[j]);
        const float* srow = g_nb + (size_t)c * CC + lane;
        acc[0] = fmaf(__ldg(srow),      v, acc[0]);
        acc[1] = fmaf(__ldg(srow + 32), v, acc[1]);
        acc[2] = fmaf(__ldg(srow + 64), v, acc[2]);
        acc[3] = fmaf(__ldg(srow + 96), v, acc[3]);
    }
#pragma unroll
    for (int i = 0; i < 4; i++) {
        __nv_bfloat16 hi, lo;
        split_bf16(acc[i], hi, lo);
        g_agh[(size_t)r * CC + lane + i * 32] = hi;
        g_agl[(size_t)r * CC + lane + i * 32] = lo;
    }
}

// ---------------------------------------------------------------------------
// Lift stage 1 (writes split bf16) + LayerNorm
// ---------------------------------------------------------------------------
__global__ void lift_hidden_kernel(const float* __restrict__ x,
                                   const float* __restrict__ w1,
                                   const float* __restrict__ b1) {
    int idx = blockIdx.x * blockDim.x + threadIdx.x;
    if (idx >= NN * CC) return;
    int n = idx >> 7;
    int c = idx & 127;
    const float* xr = x + (size_t)n * 9 + 3;
    float acc = b1[c];
#pragma unroll
    for (int i = 0; i < 6; i++)
        acc = fmaf(xr[i], w1[i * CC + c], acc);
    float v = gelu_f(acc);
    __nv_bfloat16 hi, lo;
    split_bf16(v, hi, lo);
    g_uh[idx] = hi;
    g_ul[idx] = lo;
}

__global__ void ln_kernel(const float* __restrict__ h,
                          const float* __restrict__ g,
                          const float* __restrict__ b,
                          float* __restrict__ out) {
    int n = blockIdx.x * 8 + (threadIdx.x >> 5);
    if (n >= NN) return;
    int lane = threadIdx.x & 31;
    const float* r = h + (size_t)n * CC;
    float v[4];
    float s = 0.f;
#pragma unroll
    for (int i = 0; i < 4; i++) { v[i] = r[lane + i * 32]; s += v[i]; }
#pragma unroll
    for (int o = 16; o; o >>= 1) s += __shfl_xor_sync(0xffffffffu, s, o);
    float mu = s * (1.f / 128.f);
    float q = 0.f;
#pragma unroll
    for (int i = 0; i < 4; i++) { float d = v[i] - mu; q = fmaf(d, d, q); }
#pragma unroll
    for (int o = 16; o; o >>= 1) q += __shfl_xor_sync(0xffffffffu, q, o);
    float inv = rsqrtf(q * (1.f / 128.f) + 1e-5f);
#pragma unroll
    for (int i = 0; i < 4; i++) {
        int c = lane + i * 32;
        out[(size_t)n * CC + c] = fmaf((v[i] - mu) * inv, g[c], b[c]);
    }
}

// ---------------------------------------------------------------------------
extern "C" void kernel_launch(void* const* d_in, const int* in_sizes, int n_in,
                              void* d_out, int out_size) {
    const float* x   = (const float*)d_in[0];
    const int*   ei  = (const int*)d_in[1];
    const float* ev  = (const float*)d_in[2];
    const float* lw1 = (const float*)d_in[3];
    const float* lb1 = (const float*)d_in[4];
    const float* lw2 = (const float*)d_in[5];
    const float* lb2 = (const float*)d_in[6];
    const float* sw  = (const float*)d_in[7];
    const float* sb  = (const float*)d_in[8];
    const float* nw  = (const float*)d_in[9];
    const float* nbw = (const float*)d_in[10];
    const float* gw1 = (const float*)d_in[11];
    const float* gb1 = (const float*)d_in[12];
    const float* gw2 = (const float*)d_in[13];
    const float* gb2 = (const float*)d_in[14];
    const float* ng  = (const float*)d_in[15];
    const float* nbt = (const float*)d_in[16];
    float* out = (float*)d_out;

    float *h, *nbuf;
    cudaGetSymbolAddress((void**)&h, g_h);
    cudaGetSymbolAddress((void**)&nbuf, g_nb);
    __nv_bfloat16 *wbh, *wbl, *uh, *ul, *hh, *hl, *sfh, *sfl, *agh, *agl;
    cudaGetSymbolAddress((void**)&wbh, g_wbh);
    cudaGetSymbolAddress((void**)&wbl, g_wbl);
    cudaGetSymbolAddress((void**)&uh, g_uh);
    cudaGetSymbolAddress((void**)&ul, g_ul);
    cudaGetSymbolAddress((void**)&hh, g_hh);
    cudaGetSymbolAddress((void**)&hl, g_hl);
    cudaGetSymbolAddress((void**)&sfh, g_sfh);
    cudaGetSymbolAddress((void**)&sfl, g_sfl);
    cudaGetSymbolAddress((void**)&agh, g_agh);
    cudaGetSymbolAddress((void**)&agl, g_agl);

    cudaFuncSetAttribute(gemm_mma<0, 0, 1, 1>, cudaFuncAttributeMaxDynamicSharedMemorySize, SM_TOTAL);
    cudaFuncSetAttribute(gemm_mma<1, 0, 0, 1>, cudaFuncAttributeMaxDynamicSharedMemorySize, SM_TOTAL);
    cudaFuncSetAttribute(gemm_mma<0, 1, 1, 1>, cudaFuncAttributeMaxDynamicSharedMemorySize, SM_TOTAL);
    cudaFuncSetAttribute(gemm_ns, cudaFuncAttributeMaxDynamicSharedMemorySize, SM_TOTAL);

    const int GB = (NN + 127) / 128;

    // Pre-split weights + CSR build (once per launch)
    wconv_kernel<<<(WSLOTS * 16384 + 255) / 256, 256>>>(lw2, sw, nw, gw1, gw2);
    k_zero_cnt<<<SCAN_BLOCKS, 256>>>();
    k_count<<<(EE + 255) / 256, 256>>>(ei);
    k_blocksum<<<SCAN_BLOCKS, 256>>>();
    k_scan_bsum<<<1, 512>>>();
    k_rowstart<<<SCAN_BLOCKS, 256>>>();
    k_fill<<<(EE + 255) / 256, 256>>>(ei, ev);

    // Lift: hidden (split) -> h (fp32 + split)
    lift_hidden_kernel<<<(NN * CC + 255) / 256, 256>>>(x, lw1, lb1);
    gemm_mma<0, 0, 1, 1><<<GB, 256, SM_TOTAL>>>(uh, ul, nullptr, nullptr,
                                                wbh, wbl, lb2, nullptr, h, hh, hl, 1);

    for (int l = 0; l < 2; l++) {
        const __nv_bfloat16* nh = wbh + (size_t)(1 + 5 * l) * 16384;
        const __nv_bfloat16* nl = wbl + (size_t)(1 + 5 * l) * 16384;
        const __nv_bfloat16* sh_ = wbh + (size_t)(2 + 5 * l) * 16384;
        const __nv_bfloat16* sl_ = wbl + (size_t)(2 + 5 * l) * 16384;
        const __nv_bfloat16* g1h = wbh + (size_t)(3 + 5 * l) * 16384;
        const __nv_bfloat16* g1l = wbl + (size_t)(3 + 5 * l) * 16384;
        const __nv_bfloat16* g2h = wbh + (size_t)(5 + 5 * l) * 16384;
        const __nv_bfloat16* g2l = wbl + (size_t)(5 + 5 * l) * 16384;

        // neighbor (fp32 for gather) + self (split)
        gemm_ns<<<GB, 256, SM_TOTAL>>>(hh, hl, nh, nl, nbw + l * CC, nbuf,
                                       sh_, sl_, sb + l * CC, sfh, sfl);
        // aggr (split) = pull-gather
        k_aggr<<<(NN + 7) / 8, 256>>>();
        // u = gelu([self_f, aggr] @ Wg1 + bg1)  (split)
        gemm_mma<1, 0, 0, 1><<<GB, 256, SM_TOTAL>>>(sfh, sfl, agh, agl,
                                                    g1h, g1l, gb1 + l * CC, nullptr,
                                                    nullptr, uh, ul, 2);
        // h = h + u @ Wg2 + bg2  (fp32 + split)
        gemm_mma<0, 1, 1, 1><<<GB, 256, SM_TOTAL>>>(uh, ul, nullptr, nullptr,
                                                    g2h, g2l, gb2 + l * CC, h, h, hh, hl, 1);
    }

    ln_kernel<<<(NN + 7) / 8, 256>>>(h, ng, nbt, out);
}

// round 7
// speedup vs baseline: 1.0489x; 1.0489x over previous
#include <cuda_runtime.h>
#include <cuda_bf16.h>
#include <math.h>
#include <stdint.h>

#define NN 100000
#define EE 1600000
#define CC 128
#define NTILES ((NN + 127) / 128)       // 782
#define PGRID 148
#define SCAN_BLOCKS ((NN + 255) / 256)  // 391

// ---------------------------------------------------------------------------
// Scratch (allocation-free rule: __device__ globals)
// ---------------------------------------------------------------------------
__device__ float g_h[(size_t)NN * CC];    // fp32 h (resid + LN)
__device__ float g_nb[(size_t)NN * CC];   // fp32 neighbor; reused as gate1 tmp

__device__ __nv_bfloat16 g_uh[(size_t)NN * CC],  g_ul[(size_t)NN * CC];
__device__ __nv_bfloat16 g_hh[(size_t)NN * CC],  g_hl[(size_t)NN * CC];
__device__ __nv_bfloat16 g_sfh[(size_t)NN * CC], g_sfl[(size_t)NN * CC];
__device__ __nv_bfloat16 g_agh[(size_t)NN * CC], g_agl[(size_t)NN * CC];

__device__ float g_zero[CC];              // zero-initialized bias

// CSR scratch
__device__ int   g_cnt[NN];
__device__ int   g_rowstart[NN + 1];
__device__ int   g_cursor[NN];
__device__ int   g_bsum[SCAN_BLOCKS];
__device__ int   g_boff[SCAN_BLOCKS];
__device__ int   g_ecol[EE];
__device__ float g_eval[EE];

// Pre-converted bf16 weight tiles (hi/lo split), layout [slot][n][k]
#define WSLOTS 11
__device__ __nv_bfloat16 g_wbh[(size_t)WSLOTS * 16384];
__device__ __nv_bfloat16 g_wbl[(size_t)WSLOTS * 16384];

__device__ __forceinline__ float gelu_f(float v) {
    return 0.5f * v * (1.0f + erff(v * 0.7071067811865475f));
}
__device__ __forceinline__ void split_bf16(float v, __nv_bfloat16& hi, __nv_bfloat16& lo) {
    hi = __float2bfloat16(v);
    lo = __float2bfloat16(v - __bfloat162float(hi));
}

// ---------------------------------------------------------------------------
// mma.sync / cp.async helpers
// ---------------------------------------------------------------------------
__device__ __forceinline__ void ldsm_x4(uint32_t* r, uint32_t addr) {
    asm volatile("ldmatrix.sync.aligned.m8n8.x4.shared.b16 {%0,%1,%2,%3}, [%4];"
                 : "=r"(r[0]), "=r"(r[1]), "=r"(r[2]), "=r"(r[3]) : "r"(addr));
}
__device__ __forceinline__ void mma16816(float* d, const uint32_t* a, const uint32_t* b) {
    asm volatile(
        "mma.sync.aligned.m16n8k16.row.col.f32.bf16.bf16.f32 "
        "{%0,%1,%2,%3}, {%4,%5,%6,%7}, {%8,%9}, {%0,%1,%2,%3};"
        : "+f"(d[0]), "+f"(d[1]), "+f"(d[2]), "+f"(d[3])
        : "r"(a[0]), "r"(a[1]), "r"(a[2]), "r"(a[3]), "r"(b[0]), "r"(b[1]));
}
__device__ __forceinline__ void cp16(uint32_t dst, const void* src, int srcsize) {
    asm volatile("cp.async.cg.shared.global [%0], [%1], 16, %2;"
                 :: "r"(dst), "l"(src), "r"(srcsize) : "memory");
}
__device__ __forceinline__ void cp_commit() {
    asm volatile("cp.async.commit_group;" ::: "memory");
}
__device__ __forceinline__ void cp_wait_all() {
    asm volatile("cp.async.wait_group 0;" ::: "memory");
}

// ---------------------------------------------------------------------------
// Smem layout: B resident (hi/lo) + A double buffer (hi/lo each).
// ---------------------------------------------------------------------------
#define ROWB 272
#define TILEB (128 * ROWB)          // 34816
#define SM_BH 0
#define SM_BL TILEB
#define SM_A0 (2 * TILEB)           // A0H, A0L
#define SM_A1 (4 * TILEB)           // A1H, A1L
#define SM_TOTAL (6 * TILEB)        // 208896

// 3-term bf16-split MMA over one staged 128-K tile.
__device__ __forceinline__ void mma_chunk(float acc[2][8][4], uint32_t aH,
                                          uint32_t aL, uint32_t bH, uint32_t bL) {
#pragma unroll
    for (int ks = 0; ks < 8; ks++) {
        uint32_t ah[2][4], al[2][4], bh[4][4], bl[4][4];
        ldsm_x4(ah[0], aH + ks * 32);
        ldsm_x4(ah[1], aH + ks * 32 + 16 * ROWB);
        ldsm_x4(al[0], aL + ks * 32);
        ldsm_x4(al[1], aL + ks * 32 + 16 * ROWB);
#pragma unroll
        for (int np = 0; np < 4; np++) {
            ldsm_x4(bh[np], bH + ks * 32 + np * 16 * ROWB);
            ldsm_x4(bl[np], bL + ks * 32 + np * 16 * ROWB);
        }
#pragma unroll
        for (int mi = 0; mi < 2; mi++)
#pragma unroll
            for (int nt = 0; nt < 8; nt++) {
                uint32_t bbh[2] = { bh[nt >> 1][(nt & 1) * 2], bh[nt >> 1][(nt & 1) * 2 + 1] };
                uint32_t bbl[2] = { bl[nt >> 1][(nt & 1) * 2], bl[nt >> 1][(nt & 1) * 2 + 1] };
                mma16816(acc[mi][nt], ah[mi], bbh);
                mma16816(acc[mi][nt], ah[mi], bbl);
                mma16816(acc[mi][nt], al[mi], bbh);
            }
    }
}

// Stage pre-split A tile (pure async copies; zfill OOB rows).
__device__ __forceinline__ void stage_A(uint32_t abase, const __nv_bfloat16* __restrict__ Ah,
                                        const __nv_bfloat16* __restrict__ Al,
                                        int m0, int tid) {
#pragma unroll
    for (int i = 0; i < 8; i++) {
        int ci = tid + i * 256;
        int row = ci >> 4, ch = ci & 15;
        int gm = m0 + row;
        int ss = (gm < NN) ? 16 : 0;
        int gms = (gm < NN) ? gm : (NN - 1);
        uint32_t off = (uint32_t)(row * ROWB + ch * 16);
        cp16(abase + off, Ah + (size_t)gms * 128 + ch * 8, ss);
        cp16(abase + TILEB + off, Al + (size_t)gms * 128 + ch * 8, ss);
    }
}
__device__ __forceinline__ void stage_B(uint32_t sb, const __nv_bfloat16* __restrict__ Bh,
                                        const __nv_bfloat16* __restrict__ Bl, int tid) {
#pragma unroll
    for (int i = 0; i < 8; i++) {
        int ci = tid + i * 256;
        int row = ci >> 4, ch = ci & 15;
        uint32_t off = (uint32_t)(row * ROWB + ch * 16);
        cp16(sb + SM_BH + off, Bh + ci * 8, 16);
        cp16(sb + SM_BL + off, Bl + ci * 8, 16);
    }
}

// ---------------------------------------------------------------------------
// Persistent GEMM: Out = act(A @ W + bias [+preR]) [+postR]
// RESID: 0=none, 1=post-activation, 2=pre-activation.
// ---------------------------------------------------------------------------
template <int GELU, int RESID, int WF32, int WSPLIT>
__global__ void __launch_bounds__(256, 1) gemm_pers(
    const __nv_bfloat16* __restrict__ Ah, const __nv_bfloat16* __restrict__ Al,
    const __nv_bfloat16* __restrict__ Bh, const __nv_bfloat16* __restrict__ Bl,
    const float* __restrict__ bias, const float* __restrict__ R,
    float* __restrict__ OutF, __nv_bfloat16* __restrict__ OutH,
    __nv_bfloat16* __restrict__ OutL) {
    extern __shared__ __align__(16) char smem[];
    const uint32_t sb = (uint32_t)__cvta_generic_to_shared(smem);
    const int tid = threadIdx.x;
    const int lane = tid & 31;
    const int warp_m = (tid >> 5) >> 1;
    const int warp_n = (tid >> 5) & 1;

    const uint32_t a_lane = (uint32_t)(((lane & 7) + ((lane >> 3) & 1) * 8) * ROWB +
                                       (lane >> 4) * 16) +
                            (uint32_t)(warp_m * 32 * ROWB);
    const uint32_t b_lane = (uint32_t)(((lane & 7) + ((lane >> 4) & 1) * 8) * ROWB +
                                       ((lane >> 3) & 1) * 16) +
                            (uint32_t)(warp_n * 64 * ROWB);
    const uint32_t bH = sb + SM_BH + b_lane;
    const uint32_t bL = sb + SM_BL + b_lane;

    // bias registers (constant across tiles)
    float b0[8], b1[8];
#pragma unroll
    for (int nt = 0; nt < 8; nt++) {
        int col = warp_n * 64 + nt * 8 + (lane & 3) * 2;
        b0[nt] = __ldg(bias + col);
        b1[nt] = __ldg(bias + col + 1);
    }

    // Prologue: resident B + first A tile
    stage_B(sb, Bh, Bl, tid);
    int tile = blockIdx.x;
    if (tile < NTILES) stage_A(sb + SM_A0, Ah, Al, tile * 128, tid);
    cp_commit();
    cp_wait_all();
    __syncthreads();

    int buf = 0;
    for (; tile < NTILES; tile += PGRID) {
        const int m0 = tile * 128;
        const int nxt = tile + PGRID;
        if (nxt < NTILES)
            stage_A(sb + (buf ? SM_A0 : SM_A1), Ah, Al, nxt * 128, tid);
        cp_commit();

        float acc[2][8][4];
#pragma unroll
        for (int mi = 0; mi < 2; mi++)
#pragma unroll
            for (int nt = 0; nt < 8; nt++)
#pragma unroll
                for (int e = 0; e < 4; e++) acc[mi][nt][e] = 0.0f;

        const uint32_t aB = sb + (buf ? SM_A1 : SM_A0);
        mma_chunk(acc, aB + a_lane, aB + TILEB + a_lane, bH, bL);

        // Epilogue
#pragma unroll
        for (int mi = 0; mi < 2; mi++) {
            int r0 = m0 + warp_m * 32 + mi * 16 + (lane >> 2);
#pragma unroll
            for (int half = 0; half < 2; half++) {
                int r = r0 + half * 8;
                if (r >= NN) continue;
                const float* rrow = RESID ? (R + (size_t)r * 128) : nullptr;
#pragma unroll
                for (int nt = 0; nt < 8; nt++) {
                    int col = warp_n * 64 + nt * 8 + (lane & 3) * 2;
                    float x0 = acc[mi][nt][half * 2 + 0] + b0[nt];
                    float x1 = acc[mi][nt][half * 2 + 1] + b1[nt];
                    float2 rr;
                    if (RESID) rr = *(const float2*)(rrow + col);
                    if (RESID == 2) { x0 += rr.x; x1 += rr.y; }
                    if (GELU) { x0 = gelu_f(x0); x1 = gelu_f(x1); }
                    if (RESID == 1) { x0 += rr.x; x1 += rr.y; }
                    if (WF32)
                        *(float2*)(OutF + (size_t)r * 128 + col) = make_float2(x0, x1);
                    if (WSPLIT) {
                        __nv_bfloat16 h0, l0, h1, l1;
                        split_bf16(x0, h0, l0);
                        split_bf16(x1, h1, l1);
                        *(__nv_bfloat162*)(OutH + (size_t)r * 128 + col) =
                            __nv_bfloat162(h0, h1);
                        *(__nv_bfloat162*)(OutL + (size_t)r * 128 + col) =
                            __nv_bfloat162(l0, l1);
                    }
                }
            }
        }
        cp_wait_all();
        __syncthreads();   // all warps done with current A buf; prefetched buf ready
        buf ^= 1;
    }
}

// ---------------------------------------------------------------------------
// Weight conversion: fp32 W[K,N] -> bf16 hi/lo B[N,K]
// ---------------------------------------------------------------------------
__global__ void wconv_kernel(const float* __restrict__ lw2,
                             const float* __restrict__ sw,
                             const float* __restrict__ nw,
                             const float* __restrict__ gw1,
                             const float* __restrict__ gw2) {
    int idx = blockIdx.x * blockDim.x + threadIdx.x;
    if (idx >= WSLOTS * 16384) return;
    int slot = idx >> 14;
    int within = idx & 16383;
    int n = within >> 7;
    int k = within & 127;
    const float* src;
    if (slot == 0) {
        src = lw2 + k * 128 + n;
    } else {
        int l = (slot - 1) / 5, j = (slot - 1) % 5;
        if (j == 0)      src = nw  + (size_t)l * 16384 + k * 128 + n;
        else if (j == 1) src = sw  + (size_t)l * 16384 + k * 128 + n;
        else if (j == 2) src = gw1 + (size_t)l * 32768 + k * 128 + n;
        else if (j == 3) src = gw1 + (size_t)l * 32768 + 16384 + k * 128 + n;
        else             src = gw2 + (size_t)l * 16384 + k * 128 + n;
    }
    __nv_bfloat16 hi, lo;
    split_bf16(*src, hi, lo);
    g_wbh[idx] = hi;
    g_wbl[idx] = lo;
}

// ---------------------------------------------------------------------------
// CSR build
// ---------------------------------------------------------------------------
__global__ void k_zero_cnt() {
    int i = blockIdx.x * blockDim.x + threadIdx.x;
    if (i < NN) g_cnt[i] = 0;
}
__global__ void k_count(const int* __restrict__ ei) {
    int e = blockIdx.x * blockDim.x + threadIdx.x;
    if (e < EE) atomicAdd(&g_cnt[ei[e]], 1);
}
__global__ void k_blocksum() {
    __shared__ int sh[256];
    int i = blockIdx.x * 256 + threadIdx.x;
    int v = (i < NN) ? g_cnt[i] : 0;
    sh[threadIdx.x] = v;
    __syncthreads();
    for (int s = 128; s; s >>= 1) {
        if (threadIdx.x < s) sh[threadIdx.x] += sh[threadIdx.x + s];
        __syncthreads();
    }
    if (threadIdx.x == 0) g_bsum[blockIdx.x] = sh[0];
}
__global__ void k_scan_bsum() {
    __shared__ int sh[512];
    int t = threadIdx.x;
    sh[t] = (t < SCAN_BLOCKS) ? g_bsum[t] : 0;
    __syncthreads();
    for (int off = 1; off < 512; off <<= 1) {
        int v = (t >= off) ? sh[t - off] : 0;
        __syncthreads();
        sh[t] += v;
        __syncthreads();
    }
    if (t < SCAN_BLOCKS) g_boff[t] = sh[t] - g_bsum[t];
}
__global__ void k_rowstart() {
    __shared__ int sh[256];
    int i = blockIdx.x * 256 + threadIdx.x;
    int v = (i < NN) ? g_cnt[i] : 0;
    sh[threadIdx.x] = v;
    __syncthreads();
    for (int off = 1; off < 256; off <<= 1) {
        int u = (threadIdx.x >= off) ? sh[threadIdx.x - off] : 0;
        __syncthreads();
        sh[threadIdx.x] += u;
        __syncthreads();
    }
    if (i < NN) {
        int excl = sh[threadIdx.x] - v + g_boff[blockIdx.x];
        g_rowstart[i] = excl;
        g_cursor[i] = excl;
        if (i == NN - 1) g_rowstart[NN] = excl + v;
    }
}
__global__ void k_fill(const int* __restrict__ ei, const float* __restrict__ ev) {
    int e = blockIdx.x * blockDim.x + threadIdx.x;
    if (e >= EE) return;
    int row = ei[e];
    int pos = atomicAdd(&g_cursor[row], 1);
    g_ecol[pos] = ei[EE + e];
    g_eval[pos] = ev[e];
}

// ---------------------------------------------------------------------------
// Pull aggregation: one warp per row; writes split bf16.
// ---------------------------------------------------------------------------
__global__ void k_aggr() {
    int r = blockIdx.x * 8 + (threadIdx.x >> 5);
    if (r >= NN) return;
    int lane = threadIdx.x & 31;
    int s = g_rowstart[r];
    int e = g_rowstart[r + 1];
    float acc[4] = {0.f, 0.f, 0.f, 0.f};
    for (int j = s; j < e; j++) {
        int c = __ldg(&g_ecol[j]);
        float v = __ldg(&g_eval[j]);
        const float* srow = g_nb + (size_t)c * CC + lane;
        acc[0] = fmaf(__ldg(srow),      v, acc[0]);
        acc[1] = fmaf(__ldg(srow + 32), v, acc[1]);
        acc[2] = fmaf(__ldg(srow + 64), v, acc[2]);
        acc[3] = fmaf(__ldg(srow + 96), v, acc[3]);
    }
#pragma unroll
    for (int i = 0; i < 4; i++) {
        __nv_bfloat16 hi, lo;
        split_bf16(acc[i], hi, lo);
        g_agh[(size_t)r * CC + lane + i * 32] = hi;
        g_agl[(size_t)r * CC + lane + i * 32] = lo;
    }
}

// ---------------------------------------------------------------------------
// Lift stage 1 (split output) + LayerNorm
// ---------------------------------------------------------------------------
__global__ void lift_hidden_kernel(const float* __restrict__ x,
                                   const float* __restrict__ w1,
                                   const float* __restrict__ b1) {
    int idx = blockIdx.x * blockDim.x + threadIdx.x;
    if (idx >= NN * CC) return;
    int n = idx >> 7;
    int c = idx & 127;
    const float* xr = x + (size_t)n * 9 + 3;
    float acc = b1[c];
#pragma unroll
    for (int i = 0; i < 6; i++)
        acc = fmaf(xr[i], w1[i * CC + c], acc);
    float v = gelu_f(acc);
    __nv_bfloat16 hi, lo;
    split_bf16(v, hi, lo);
    g_uh[idx] = hi;
    g_ul[idx] = lo;
}

__global__ void ln_kernel(const float* __restrict__ h,
                          const float* __restrict__ g,
                          const float* __restrict__ b,
                          float* __restrict__ out) {
    int n = blockIdx.x * 8 + (threadIdx.x >> 5);
    if (n >= NN) return;
    int lane = threadIdx.x & 31;
    const float* r = h + (size_t)n * CC;
    float v[4];
    float s = 0.f;
#pragma unroll
    for (int i = 0; i < 4; i++) { v[i] = r[lane + i * 32]; s += v[i]; }
#pragma unroll
    for (int o = 16; o; o >>= 1) s += __shfl_xor_sync(0xffffffffu, s, o);
    float mu = s * (1.f / 128.f);
    float q = 0.f;
#pragma unroll
    for (int i = 0; i < 4; i++) { float d = v[i] - mu; q = fmaf(d, d, q); }
#pragma unroll
    for (int o = 16; o; o >>= 1) q += __shfl_xor_sync(0xffffffffu, q, o);
    float inv = rsqrtf(q * (1.f / 128.f) + 1e-5f);
#pragma unroll
    for (int i = 0; i < 4; i++) {
        int c = lane + i * 32;
        out[(size_t)n * CC + c] = fmaf((v[i] - mu) * inv, g[c], b[c]);
    }
}

// ---------------------------------------------------------------------------
extern "C" void kernel_launch(void* const* d_in, const int* in_sizes, int n_in,
                              void* d_out, int out_size) {
    const float* x   = (const float*)d_in[0];
    const int*   ei  = (const int*)d_in[1];
    const float* ev  = (const float*)d_in[2];
    const float* lw1 = (const float*)d_in[3];
    const float* lb1 = (const float*)d_in[4];
    const float* lw2 = (const float*)d_in[5];
    const float* lb2 = (const float*)d_in[6];
    const float* sw  = (const float*)d_in[7];
    const float* sb  = (const float*)d_in[8];
    const float* nw  = (const float*)d_in[9];
    const float* nbw = (const float*)d_in[10];
    const float* gw1 = (const float*)d_in[11];
    const float* gb1 = (const float*)d_in[12];
    const float* gw2 = (const float*)d_in[13];
    const float* gb2 = (const float*)d_in[14];
    const float* ng  = (const float*)d_in[15];
    const float* nbt = (const float*)d_in[16];
    float* out = (float*)d_out;

    float *h, *nbuf, *zero;
    cudaGetSymbolAddress((void**)&h, g_h);
    cudaGetSymbolAddress((void**)&nbuf, g_nb);
    cudaGetSymbolAddress((void**)&zero, g_zero);
    __nv_bfloat16 *wbh, *wbl, *uh, *ul, *hh, *hl, *sfh, *sfl, *agh, *agl;
    cudaGetSymbolAddress((void**)&wbh, g_wbh);
    cudaGetSymbolAddress((void**)&wbl, g_wbl);
    cudaGetSymbolAddress((void**)&uh, g_uh);
    cudaGetSymbolAddress((void**)&ul, g_ul);
    cudaGetSymbolAddress((void**)&hh, g_hh);
    cudaGetSymbolAddress((void**)&hl, g_hl);
    cudaGetSymbolAddress((void**)&sfh, g_sfh);
    cudaGetSymbolAddress((void**)&sfl, g_sfl);
    cudaGetSymbolAddress((void**)&agh, g_agh);
    cudaGetSymbolAddress((void**)&agl, g_agl);

    cudaFuncSetAttribute(gemm_pers<0, 0, 1, 1>, cudaFuncAttributeMaxDynamicSharedMemorySize, SM_TOTAL);
    cudaFuncSetAttribute(gemm_pers<0, 0, 1, 0>, cudaFuncAttributeMaxDynamicSharedMemorySize, SM_TOTAL);
    cudaFuncSetAttribute(gemm_pers<0, 0, 0, 1>, cudaFuncAttributeMaxDynamicSharedMemorySize, SM_TOTAL);
    cudaFuncSetAttribute(gemm_pers<1, 2, 0, 1>, cudaFuncAttributeMaxDynamicSharedMemorySize, SM_TOTAL);
    cudaFuncSetAttribute(gemm_pers<0, 1, 1, 1>, cudaFuncAttributeMaxDynamicSharedMemorySize, SM_TOTAL);

    // Pre-split weights + CSR build (once per launch)
    wconv_kernel<<<(WSLOTS * 16384 + 255) / 256, 256>>>(lw2, sw, nw, gw1, gw2);
    k_zero_cnt<<<SCAN_BLOCKS, 256>>>();
    k_count<<<(EE + 255) / 256, 256>>>(ei);
    k_blocksum<<<SCAN_BLOCKS, 256>>>();
    k_scan_bsum<<<1, 512>>>();
    k_rowstart<<<SCAN_BLOCKS, 256>>>();
    k_fill<<<(EE + 255) / 256, 256>>>(ei, ev);

    // Lift: hidden (split) -> h (fp32 + split)
    lift_hidden_kernel<<<(NN * CC + 255) / 256, 256>>>(x, lw1, lb1);
    gemm_pers<0, 0, 1, 1><<<PGRID, 256, SM_TOTAL>>>(uh, ul, wbh, wbl, lb2,
                                                    nullptr, h, hh, hl);

    for (int l = 0; l < 2; l++) {
        const __nv_bfloat16* nh  = wbh + (size_t)(1 + 5 * l) * 16384;
        const __nv_bfloat16* nl  = wbl + (size_t)(1 + 5 * l) * 16384;
        const __nv_bfloat16* sh_ = wbh + (size_t)(2 + 5 * l) * 16384;
        const __nv_bfloat16* sl_ = wbl + (size_t)(2 + 5 * l) * 16384;
        const __nv_bfloat16* g1ah = wbh + (size_t)(3 + 5 * l) * 16384;
        const __nv_bfloat16* g1al = wbl + (size_t)(3 + 5 * l) * 16384;
        const __nv_bfloat16* g1bh = wbh + (size_t)(4 + 5 * l) * 16384;
        const __nv_bfloat16* g1bl = wbl + (size_t)(4 + 5 * l) * 16384;
        const __nv_bfloat16* g2h = wbh + (size_t)(5 + 5 * l) * 16384;
        const __nv_bfloat16* g2l = wbl + (size_t)(5 + 5 * l) * 16384;

        // neighbor = h @ Wn + bn  (fp32, consumed by k_aggr)
        gemm_pers<0, 0, 1, 0><<<PGRID, 256, SM_TOTAL>>>(hh, hl, nh, nl,
                                                        nbw + l * CC, nullptr,
                                                        nbuf, nullptr, nullptr);
        // aggr (split) = pull-gather of neighbor
        k_aggr<<<(NN + 7) / 8, 256>>>();
        // self_f = h @ Ws + bs  (split)
        gemm_pers<0, 0, 0, 1><<<PGRID, 256, SM_TOTAL>>>(hh, hl, sh_, sl_,
                                                        sb + l * CC, nullptr,
                                                        nullptr, sfh, sfl);
        // tmp = self_f @ Wg1a + bg1   (fp32; nbuf is free after k_aggr)
        gemm_pers<0, 0, 1, 0><<<PGRID, 256, SM_TOTAL>>>(sfh, sfl, g1ah, g1al,
                                                        gb1 + l * CC, nullptr,
                                                        nbuf, nullptr, nullptr);
        // u = gelu(aggr @ Wg1b + tmp)  (split; pre-act resid, zero bias)
        gemm_pers<1, 2, 0, 1><<<PGRID, 256, SM_TOTAL>>>(agh, agl, g1bh, g1bl,
                                                        zero, nbuf,
                                                        nullptr, uh, ul);
        // h = h + u @ Wg2 + bg2  (fp32 + split)
        gemm_pers<0, 1, 1, 1><<<PGRID, 256, SM_TOTAL>>>(uh, ul, g2h, g2l,
                                                        gb2 + l * CC, h, h, hh, hl);
    }

    ln_kernel<<<(NN + 7) / 8, 256>>>(h, ng, nbt, out);
}

// round 8
// speedup vs baseline: 1.0931x; 1.0421x over previous
#include <cuda_runtime.h>
#include <cuda_bf16.h>
#include <math.h>
#include <stdint.h>

#define NN 100000
#define EE 1600000
#define CC 128
#define NTILES ((NN + 127) / 128)       // 782
#define PGRID 148
#define SCAN_BLOCKS ((NN + 255) / 256)  // 391

// ---------------------------------------------------------------------------
// Scratch (allocation-free rule: __device__ globals)
// ---------------------------------------------------------------------------
__device__ float g_h[(size_t)NN * CC];     // fp32 h
__device__ float g_nb[(size_t)NN * CC];    // fp32 neighbor (gathered by k_aggr)
__device__ float g_tmp[(size_t)NN * CC];   // fp32 gate1a partial

__device__ __nv_bfloat16 g_uh[(size_t)NN * CC],  g_ul[(size_t)NN * CC];   // lift-hidden / u
__device__ __nv_bfloat16 g_agh[(size_t)NN * CC], g_agl[(size_t)NN * CC];  // aggr

__device__ float g_zero[CC];               // zero bias

// CSR scratch
__device__ int   g_cnt[NN];
__device__ int   g_rowstart[NN + 1];
__device__ int   g_cursor[NN];
__device__ int   g_bsum[SCAN_BLOCKS];
__device__ int   g_boff[SCAN_BLOCKS];
__device__ int   g_ecol[EE];
__device__ float g_eval[EE];

// Pre-converted bf16 weight tiles (hi/lo split), layout [slot][n][k]
#define WSLOTS 11
__device__ __nv_bfloat16 g_wbh[(size_t)WSLOTS * 16384];
__device__ __nv_bfloat16 g_wbl[(size_t)WSLOTS * 16384];

__device__ __forceinline__ float gelu_f(float v) {
    return 0.5f * v * (1.0f + erff(v * 0.7071067811865475f));
}
__device__ __forceinline__ void split_bf16(float v, __nv_bfloat16& hi, __nv_bfloat16& lo) {
    hi = __float2bfloat16(v);
    lo = __float2bfloat16(v - __bfloat162float(hi));
}

// ---------------------------------------------------------------------------
// mma.sync / cp.async helpers
// ---------------------------------------------------------------------------
__device__ __forceinline__ void ldsm_x4(uint32_t* r, uint32_t addr) {
    asm volatile("ldmatrix.sync.aligned.m8n8.x4.shared.b16 {%0,%1,%2,%3}, [%4];"
                 : "=r"(r[0]), "=r"(r[1]), "=r"(r[2]), "=r"(r[3]) : "r"(addr));
}
__device__ __forceinline__ void mma16816(float* d, const uint32_t* a, const uint32_t* b) {
    asm volatile(
        "mma.sync.aligned.m16n8k16.row.col.f32.bf16.bf16.f32 "
        "{%0,%1,%2,%3}, {%4,%5,%6,%7}, {%8,%9}, {%0,%1,%2,%3};"
        : "+f"(d[0]), "+f"(d[1]), "+f"(d[2]), "+f"(d[3])
        : "r"(a[0]), "r"(a[1]), "r"(a[2]), "r"(a[3]), "r"(b[0]), "r"(b[1]));
}
__device__ __forceinline__ void cp16(uint32_t dst, const void* src, int srcsize) {
    asm volatile("cp.async.cg.shared.global [%0], [%1], 16, %2;"
                 :: "r"(dst), "l"(src), "r"(srcsize) : "memory");
}
__device__ __forceinline__ void cp_commit() {
    asm volatile("cp.async.commit_group;" ::: "memory");
}
__device__ __forceinline__ void cp_wait_all() {
    asm volatile("cp.async.wait_group 0;" ::: "memory");
}

// ---------------------------------------------------------------------------
// Smem layout (6 tiles of 34816B): A hi/lo + two B hi/lo buffers
// ---------------------------------------------------------------------------
#define ROWB 272
#define TILEB (128 * ROWB)          // 34816
#define SM_AH 0
#define SM_AL TILEB
#define SM_B0 (2 * TILEB)
#define SM_B1 (4 * TILEB)
#define SM_TOTAL (6 * TILEB)        // 208896

// 3-term bf16-split MMA over one staged 128-K tile.
__device__ __forceinline__ void mma_chunk(float acc[2][8][4], uint32_t aH,
                                          uint32_t aL, uint32_t bH, uint32_t bL) {
#pragma unroll
    for (int ks = 0; ks < 8; ks++) {
        uint32_t ah[2][4], al[2][4], bh[4][4], bl[4][4];
        ldsm_x4(ah[0], aH + ks * 32);
        ldsm_x4(ah[1], aH + ks * 32 + 16 * ROWB);
        ldsm_x4(al[0], aL + ks * 32);
        ldsm_x4(al[1], aL + ks * 32 + 16 * ROWB);
#pragma unroll
        for (int np = 0; np < 4; np++) {
            ldsm_x4(bh[np], bH + ks * 32 + np * 16 * ROWB);
            ldsm_x4(bl[np], bL + ks * 32 + np * 16 * ROWB);
        }
#pragma unroll
        for (int mi = 0; mi < 2; mi++)
#pragma unroll
            for (int nt = 0; nt < 8; nt++) {
                uint32_t bbh[2] = { bh[nt >> 1][(nt & 1) * 2], bh[nt >> 1][(nt & 1) * 2 + 1] };
                uint32_t bbl[2] = { bl[nt >> 1][(nt & 1) * 2], bl[nt >> 1][(nt & 1) * 2 + 1] };
                mma16816(acc[mi][nt], ah[mi], bbh);
                mma16816(acc[mi][nt], ah[mi], bbl);
                mma16816(acc[mi][nt], al[mi], bbh);
            }
    }
}

#define ACC_ZERO(acc)                                   \
    _Pragma("unroll")                                   \
    for (int mi = 0; mi < 2; mi++)                      \
        _Pragma("unroll")                               \
        for (int nt = 0; nt < 8; nt++)                  \
            _Pragma("unroll")                           \
            for (int e = 0; e < 4; e++) acc[mi][nt][e] = 0.0f;

// Stage fp32 A tile: LDG + inline bf16 hi/lo split + STS.
__device__ __forceinline__ void stage_A_f32(char* smem, const float* __restrict__ A,
                                            int m0, int tid) {
#pragma unroll
    for (int i = 0; i < 8; i++) {
        int ci = tid + i * 256;
        int row = ci >> 4, ch = ci & 15;
        int gm = m0 + row;
        float v[8];
        if (gm < NN) {
            float4 a = *(const float4*)(A + (size_t)gm * 128 + ch * 8);
            float4 b = *(const float4*)(A + (size_t)gm * 128 + ch * 8 + 4);
            v[0] = a.x; v[1] = a.y; v[2] = a.z; v[3] = a.w;
            v[4] = b.x; v[5] = b.y; v[6] = b.z; v[7] = b.w;
        } else {
#pragma unroll
            for (int e = 0; e < 8; e++) v[e] = 0.0f;
        }
        __align__(16) __nv_bfloat16 h8[8], l8[8];
#pragma unroll
        for (int e = 0; e < 8; e++) split_bf16(v[e], h8[e], l8[e]);
        uint32_t off = (uint32_t)(row * ROWB + ch * 16);
        *(uint4*)(smem + SM_AH + off) = *(uint4*)h8;
        *(uint4*)(smem + SM_AL + off) = *(uint4*)l8;
    }
}

// Stage pre-split A tile (pure async copies; zfill OOB rows).
__device__ __forceinline__ void stage_A_split(uint32_t abase,
                                              const __nv_bfloat16* __restrict__ Ah,
                                              const __nv_bfloat16* __restrict__ Al,
                                              int m0, int tid) {
#pragma unroll
    for (int i = 0; i < 8; i++) {
        int ci = tid + i * 256;
        int row = ci >> 4, ch = ci & 15;
        int gm = m0 + row;
        int ss = (gm < NN) ? 16 : 0;
        int gms = (gm < NN) ? gm : (NN - 1);
        uint32_t off = (uint32_t)(row * ROWB + ch * 16);
        cp16(abase + off, Ah + (size_t)gms * 128 + ch * 8, ss);
        cp16(abase + TILEB + off, Al + (size_t)gms * 128 + ch * 8, ss);
    }
}
__device__ __forceinline__ void stage_B(uint32_t bbase, const __nv_bfloat16* __restrict__ Bh,
                                        const __nv_bfloat16* __restrict__ Bl, int tid) {
#pragma unroll
    for (int i = 0; i < 8; i++) {
        int ci = tid + i * 256;
        int row = ci >> 4, ch = ci & 15;
        uint32_t off = (uint32_t)(row * ROWB + ch * 16);
        cp16(bbase + off, Bh + ci * 8, 16);
        cp16(bbase + TILEB + off, Bl + ci * 8, 16);
    }
}

// fp32 epilogue to global.
__device__ __forceinline__ void epi_f32(float acc[2][8][4], const float* __restrict__ bias,
                                        float* __restrict__ Out, int m0,
                                        int warp_m, int warp_n, int lane) {
#pragma unroll
    for (int mi = 0; mi < 2; mi++) {
        int r0 = m0 + warp_m * 32 + mi * 16 + (lane >> 2);
#pragma unroll
        for (int half = 0; half < 2; half++) {
            int r = r0 + half * 8;
            if (r >= NN) continue;
#pragma unroll
            for (int nt = 0; nt < 8; nt++) {
                int col = warp_n * 64 + nt * 8 + (lane & 3) * 2;
                float x0 = acc[mi][nt][half * 2 + 0] + __ldg(bias + col);
                float x1 = acc[mi][nt][half * 2 + 1] + __ldg(bias + col + 1);
                *(float2*)(Out + (size_t)r * 128 + col) = make_float2(x0, x1);
            }
        }
    }
}

// ---------------------------------------------------------------------------
// Fused nb+self+gate1a kernel (one A stage -> 3 MMA blocks).
//   nb   = h @ Wn + bn            -> g_nb (fp32)
//   sf   = h @ Ws + bs            -> SMEM A buffer (split, replaces h)
//   tmp  = sf @ Wg1a + bg1        -> g_tmp (fp32)
// ---------------------------------------------------------------------------
__global__ void __launch_bounds__(256, 1) gemm_nsg(
    const float* __restrict__ H,
    const __nv_bfloat16* __restrict__ Bnh, const __nv_bfloat16* __restrict__ Bnl,
    const float* __restrict__ bn, float* __restrict__ OutN,
    const __nv_bfloat16* __restrict__ Bsh, const __nv_bfloat16* __restrict__ Bsl,
    const float* __restrict__ bs,
    const __nv_bfloat16* __restrict__ Bgh, const __nv_bfloat16* __restrict__ Bgl,
    const float* __restrict__ bg, float* __restrict__ OutT) {
    extern __shared__ __align__(16) char smem[];
    const uint32_t sb = (uint32_t)__cvta_generic_to_shared(smem);
    const int tid = threadIdx.x;
    const int lane = tid & 31;
    const int warp_m = (tid >> 5) >> 1;
    const int warp_n = (tid >> 5) & 1;
    const int m0 = blockIdx.x * 128;

    const uint32_t a_lane = (uint32_t)(((lane & 7) + ((lane >> 3) & 1) * 8) * ROWB +
                                       (lane >> 4) * 16) +
                            (uint32_t)(warp_m * 32 * ROWB);
    const uint32_t b_lane = (uint32_t)(((lane & 7) + ((lane >> 4) & 1) * 8) * ROWB +
                                       ((lane >> 3) & 1) * 16) +
                            (uint32_t)(warp_n * 64 * ROWB);

    // Prologue: B_nb async + A (fp32 inline split)
    stage_B(sb + SM_B0, Bnh, Bnl, tid);
    cp_commit();
    stage_A_f32(smem, H, m0, tid);
    cp_wait_all();
    __syncthreads();

    // Prefetch B_self during nb MMA
    stage_B(sb + SM_B1, Bsh, Bsl, tid);
    cp_commit();

    float acc[2][8][4];
    ACC_ZERO(acc);
    mma_chunk(acc, sb + SM_AH + a_lane, sb + SM_AL + a_lane,
              sb + SM_B0 + b_lane, sb + SM_B0 + TILEB + b_lane);
    epi_f32(acc, bn, OutN, m0, warp_m, warp_n, lane);

    cp_wait_all();
    __syncthreads();                 // B1 ready, all warps past B0 reads

    // Prefetch B_g1a (into B0) during self MMA
    stage_B(sb + SM_B0, Bgh, Bgl, tid);
    cp_commit();

    ACC_ZERO(acc);
    mma_chunk(acc, sb + SM_AH + a_lane, sb + SM_AL + a_lane,
              sb + SM_B1 + b_lane, sb + SM_B1 + TILEB + b_lane);
    __syncthreads();                 // all warps done reading A (h)

    // Write self_f (+bs) split into SMEM A buffer
#pragma unroll
    for (int mi = 0; mi < 2; mi++) {
#pragma unroll
        for (int half = 0; half < 2; half++) {
            int row = warp_m * 32 + mi * 16 + (lane >> 2) + half * 8;
#pragma unroll
            for (int nt = 0; nt < 8; nt++) {
                int col = warp_n * 64 + nt * 8 + (lane & 3) * 2;
                float x0 = acc[mi][nt][half * 2 + 0] + __ldg(bs + col);
                float x1 = acc[mi][nt][half * 2 + 1] + __ldg(bs + col + 1);
                __nv_bfloat16 h0, l0, h1, l1;
                split_bf16(x0, h0, l0);
                split_bf16(x1, h1, l1);
                uint32_t off = (uint32_t)(row * ROWB + col * 2);
                *(__nv_bfloat162*)(smem + SM_AH + off) = __nv_bfloat162(h0, h1);
                *(__nv_bfloat162*)(smem + SM_AL + off) = __nv_bfloat162(l0, l1);
            }
        }
    }
    cp_wait_all();
    __syncthreads();                 // self_f visible + B_g1a ready

    ACC_ZERO(acc);
    mma_chunk(acc, sb + SM_AH + a_lane, sb + SM_AL + a_lane,
              sb + SM_B0 + b_lane, sb + SM_B0 + TILEB + b_lane);
    epi_f32(acc, bg, OutT, m0, warp_m, warp_n, lane);
}

// ---------------------------------------------------------------------------
// Persistent GEMM (pre-split A, resident B, double-buffered A).
// RESID: 0=none, 1=post-act, 2=pre-act. WF32/WSPLIT select outputs.
// ---------------------------------------------------------------------------
template <int GELU, int RESID, int WF32, int WSPLIT>
__global__ void __launch_bounds__(256, 1) gemm_pers(
    const __nv_bfloat16* __restrict__ Ah, const __nv_bfloat16* __restrict__ Al,
    const __nv_bfloat16* __restrict__ Bh, const __nv_bfloat16* __restrict__ Bl,
    const float* __restrict__ bias, const float* __restrict__ R,
    float* __restrict__ OutF, __nv_bfloat16* __restrict__ OutH,
    __nv_bfloat16* __restrict__ OutL) {
    extern __shared__ __align__(16) char smem[];
    const uint32_t sb = (uint32_t)__cvta_generic_to_shared(smem);
    const int tid = threadIdx.x;
    const int lane = tid & 31;
    const int warp_m = (tid >> 5) >> 1;
    const int warp_n = (tid >> 5) & 1;

    const uint32_t a_lane = (uint32_t)(((lane & 7) + ((lane >> 3) & 1) * 8) * ROWB +
                                       (lane >> 4) * 16) +
                            (uint32_t)(warp_m * 32 * ROWB);
    const uint32_t b_lane = (uint32_t)(((lane & 7) + ((lane >> 4) & 1) * 8) * ROWB +
                                       ((lane >> 3) & 1) * 16) +
                            (uint32_t)(warp_n * 64 * ROWB);
    // B resident in B0 slot; A double-buffered in AH/AL and B1 slots.
    const uint32_t bH = sb + SM_B0 + b_lane;
    const uint32_t bL = sb + SM_B0 + TILEB + b_lane;

    float b0[8], b1[8];
#pragma unroll
    for (int nt = 0; nt < 8; nt++) {
        int col = warp_n * 64 + nt * 8 + (lane & 3) * 2;
        b0[nt] = __ldg(bias + col);
        b1[nt] = __ldg(bias + col + 1);
    }

    stage_B(sb + SM_B0, Bh, Bl, tid);
    int tile = blockIdx.x;
    if (tile < NTILES) stage_A_split(sb + SM_AH, Ah, Al, tile * 128, tid);
    cp_commit();
    cp_wait_all();
    __syncthreads();

    int buf = 0;
    for (; tile < NTILES; tile += PGRID) {
        const int m0 = tile * 128;
        const int nxt = tile + PGRID;
        if (nxt < NTILES)
            stage_A_split(sb + (buf ? SM_AH : SM_B1), Ah, Al, nxt * 128, tid);
        cp_commit();

        float acc[2][8][4];
        ACC_ZERO(acc);
        const uint32_t aB = sb + (buf ? SM_B1 : SM_AH);
        mma_chunk(acc, aB + a_lane, aB + TILEB + a_lane, bH, bL);

#pragma unroll
        for (int mi = 0; mi < 2; mi++) {
            int r0 = m0 + warp_m * 32 + mi * 16 + (lane >> 2);
#pragma unroll
            for (int half = 0; half < 2; half++) {
                int r = r0 + half * 8;
                if (r >= NN) continue;
                const float* rrow = RESID ? (R + (size_t)r * 128) : nullptr;
#pragma unroll
                for (int nt = 0; nt < 8; nt++) {
                    int col = warp_n * 64 + nt * 8 + (lane & 3) * 2;
                    float x0 = acc[mi][nt][half * 2 + 0] + b0[nt];
                    float x1 = acc[mi][nt][half * 2 + 1] + b1[nt];
                    float2 rr;
                    if (RESID) rr = *(const float2*)(rrow + col);
                    if (RESID == 2) { x0 += rr.x; x1 += rr.y; }
                    if (GELU) { x0 = gelu_f(x0); x1 = gelu_f(x1); }
                    if (RESID == 1) { x0 += rr.x; x1 += rr.y; }
                    if (WF32)
                        *(float2*)(OutF + (size_t)r * 128 + col) = make_float2(x0, x1);
                    if (WSPLIT) {
                        __nv_bfloat16 h0, l0, h1, l1;
                        split_bf16(x0, h0, l0);
                        split_bf16(x1, h1, l1);
                        *(__nv_bfloat162*)(OutH + (size_t)r * 128 + col) =
                            __nv_bfloat162(h0, h1);
                        *(__nv_bfloat162*)(OutL + (size_t)r * 128 + col) =
                            __nv_bfloat162(l0, l1);
                    }
                }
            }
        }
        cp_wait_all();
        __syncthreads();
        buf ^= 1;
    }
}

// ---------------------------------------------------------------------------
// Weight conversion: fp32 W[K,N] -> bf16 hi/lo B[N,K]
// ---------------------------------------------------------------------------
__global__ void wconv_kernel(const float* __restrict__ lw2,
                             const float* __restrict__ sw,
                             const float* __restrict__ nw,
                             const float* __restrict__ gw1,
                             const float* __restrict__ gw2) {
    int idx = blockIdx.x * blockDim.x + threadIdx.x;
    if (idx >= WSLOTS * 16384) return;
    int slot = idx >> 14;
    int within = idx & 16383;
    int n = within >> 7;
    int k = within & 127;
    const float* src;
    if (slot == 0) {
        src = lw2 + k * 128 + n;
    } else {
        int l = (slot - 1) / 5, j = (slot - 1) % 5;
        if (j == 0)      src = nw  + (size_t)l * 16384 + k * 128 + n;
        else if (j == 1) src = sw  + (size_t)l * 16384 + k * 128 + n;
        else if (j == 2) src = gw1 + (size_t)l * 32768 + k * 128 + n;
        else if (j == 3) src = gw1 + (size_t)l * 32768 + 16384 + k * 128 + n;
        else             src = gw2 + (size_t)l * 16384 + k * 128 + n;
    }
    __nv_bfloat16 hi, lo;
    split_bf16(*src, hi, lo);
    g_wbh[idx] = hi;
    g_wbl[idx] = lo;
}

// ---------------------------------------------------------------------------
// CSR build
// ---------------------------------------------------------------------------
__global__ void k_zero_cnt() {
    int i = blockIdx.x * blockDim.x + threadIdx.x;
    if (i < NN) g_cnt[i] = 0;
}
__global__ void k_count(const int* __restrict__ ei) {
    int e = blockIdx.x * blockDim.x + threadIdx.x;
    if (e < EE) atomicAdd(&g_cnt[ei[e]], 1);
}
__global__ void k_blocksum() {
    __shared__ int sh[256];
    int i = blockIdx.x * 256 + threadIdx.x;
    int v = (i < NN) ? g_cnt[i] : 0;
    sh[threadIdx.x] = v;
    __syncthreads();
    for (int s = 128; s; s >>= 1) {
        if (threadIdx.x < s) sh[threadIdx.x] += sh[threadIdx.x + s];
        __syncthreads();
    }
    if (threadIdx.x == 0) g_bsum[blockIdx.x] = sh[0];
}
__global__ void k_scan_bsum() {
    __shared__ int sh[512];
    int t = threadIdx.x;
    sh[t] = (t < SCAN_BLOCKS) ? g_bsum[t] : 0;
    __syncthreads();
    for (int off = 1; off < 512; off <<= 1) {
        int v = (t >= off) ? sh[t - off] : 0;
        __syncthreads();
        sh[t] += v;
        __syncthreads();
    }
    if (t < SCAN_BLOCKS) g_boff[t] = sh[t] - g_bsum[t];
}
__global__ void k_rowstart() {
    __shared__ int sh[256];
    int i = blockIdx.x * 256 + threadIdx.x;
    int v = (i < NN) ? g_cnt[i] : 0;
    sh[threadIdx.x] = v;
    __syncthreads();
    for (int off = 1; off < 256; off <<= 1) {
        int u = (threadIdx.x >= off) ? sh[threadIdx.x - off] : 0;
        __syncthreads();
        sh[threadIdx.x] += u;
        __syncthreads();
    }
    if (i < NN) {
        int excl = sh[threadIdx.x] - v + g_boff[blockIdx.x];
        g_rowstart[i] = excl;
        g_cursor[i] = excl;
        if (i == NN - 1) g_rowstart[NN] = excl + v;
    }
}
__global__ void k_fill(const int* __restrict__ ei, const float* __restrict__ ev) {
    int e = blockIdx.x * blockDim.x + threadIdx.x;
    if (e >= EE) return;
    int row = ei[e];
    int pos = atomicAdd(&g_cursor[row], 1);
    g_ecol[pos] = ei[EE + e];
    g_eval[pos] = ev[e];
}

// ---------------------------------------------------------------------------
// Pull aggregation: one warp per row; writes split bf16.
// ---------------------------------------------------------------------------
__global__ void k_aggr() {
    int r = blockIdx.x * 8 + (threadIdx.x >> 5);
    if (r >= NN) return;
    int lane = threadIdx.x & 31;
    int s = g_rowstart[r];
    int e = g_rowstart[r + 1];
    float acc[4] = {0.f, 0.f, 0.f, 0.f};
    for (int j = s; j < e; j++) {
        int c = __ldg(&g_ecol[j]);
        float v = __ldg(&g_eval[j]);
        const float* srow = g_nb + (size_t)c * CC + lane;
        acc[0] = fmaf(__ldg(srow),      v, acc[0]);
        acc[1] = fmaf(__ldg(srow + 32), v, acc[1]);
        acc[2] = fmaf(__ldg(srow + 64), v, acc[2]);
        acc[3] = fmaf(__ldg(srow + 96), v, acc[3]);
    }
#pragma unroll
    for (int i = 0; i < 4; i++) {
        __nv_bfloat16 hi, lo;
        split_bf16(acc[i], hi, lo);
        g_agh[(size_t)r * CC + lane + i * 32] = hi;
        g_agl[(size_t)r * CC + lane + i * 32] = lo;
    }
}

// ---------------------------------------------------------------------------
// Lift stage 1 (split output) + LayerNorm
// ---------------------------------------------------------------------------
__global__ void lift_hidden_kernel(const float* __restrict__ x,
                                   const float* __restrict__ w1,
                                   const float* __restrict__ b1) {
    int idx = blockIdx.x * blockDim.x + threadIdx.x;
    if (idx >= NN * CC) return;
    int n = idx >> 7;
    int c = idx & 127;
    const float* xr = x + (size_t)n * 9 + 3;
    float acc = b1[c];
#pragma unroll
    for (int i = 0; i < 6; i++)
        acc = fmaf(xr[i], w1[i * CC + c], acc);
    float v = gelu_f(acc);
    __nv_bfloat16 hi, lo;
    split_bf16(v, hi, lo);
    g_uh[idx] = hi;
    g_ul[idx] = lo;
}

__global__ void ln_kernel(const float* __restrict__ h,
                          const float* __restrict__ g,
                          const float* __restrict__ b,
                          float* __restrict__ out) {
    int n = blockIdx.x * 8 + (threadIdx.x >> 5);
    if (n >= NN) return;
    int lane = threadIdx.x & 31;
    const float* r = h + (size_t)n * CC;
    float v[4];
    float s = 0.f;
#pragma unroll
    for (int i = 0; i < 4; i++) { v[i] = r[lane + i * 32]; s += v[i]; }
#pragma unroll
    for (int o = 16; o; o >>= 1) s += __shfl_xor_sync(0xffffffffu, s, o);
    float mu = s * (1.f / 128.f);
    float q = 0.f;
#pragma unroll
    for (int i = 0; i < 4; i++) { float d = v[i] - mu; q = fmaf(d, d, q); }
#pragma unroll
    for (int o = 16; o; o >>= 1) q += __shfl_xor_sync(0xffffffffu, q, o);
    float inv = rsqrtf(q * (1.f / 128.f) + 1e-5f);
#pragma unroll
    for (int i = 0; i < 4; i++) {
        int c = lane + i * 32;
        out[(size_t)n * CC + c] = fmaf((v[i] - mu) * inv, g[c], b[c]);
    }
}

// ---------------------------------------------------------------------------
extern "C" void kernel_launch(void* const* d_in, const int* in_sizes, int n_in,
                              void* d_out, int out_size) {
    const float* x   = (const float*)d_in[0];
    const int*   ei  = (const int*)d_in[1];
    const float* ev  = (const float*)d_in[2];
    const float* lw1 = (const float*)d_in[3];
    const float* lb1 = (const float*)d_in[4];
    const float* lw2 = (const float*)d_in[5];
    const float* lb2 = (const float*)d_in[6];
    const float* sw  = (const float*)d_in[7];
    const float* sb  = (const float*)d_in[8];
    const float* nw  = (const float*)d_in[9];
    const float* nbw = (const float*)d_in[10];
    const float* gw1 = (const float*)d_in[11];
    const float* gb1 = (const float*)d_in[12];
    const float* gw2 = (const float*)d_in[13];
    const float* gb2 = (const float*)d_in[14];
    const float* ng  = (const float*)d_in[15];
    const float* nbt = (const float*)d_in[16];
    float* out = (float*)d_out;

    float *h, *nbuf, *tmp, *zero;
    cudaGetSymbolAddress((void**)&h, g_h);
    cudaGetSymbolAddress((void**)&nbuf, g_nb);
    cudaGetSymbolAddress((void**)&tmp, g_tmp);
    cudaGetSymbolAddress((void**)&zero, g_zero);
    __nv_bfloat16 *wbh, *wbl, *uh, *ul, *agh, *agl;
    cudaGetSymbolAddress((void**)&wbh, g_wbh);
    cudaGetSymbolAddress((void**)&wbl, g_wbl);
    cudaGetSymbolAddress((void**)&uh, g_uh);
    cudaGetSymbolAddress((void**)&ul, g_ul);
    cudaGetSymbolAddress((void**)&agh, g_agh);
    cudaGetSymbolAddress((void**)&agl, g_agl);

    cudaFuncSetAttribute(gemm_pers<0, 0, 1, 0>, cudaFuncAttributeMaxDynamicSharedMemorySize, SM_TOTAL);
    cudaFuncSetAttribute(gemm_pers<1, 2, 0, 1>, cudaFuncAttributeMaxDynamicSharedMemorySize, SM_TOTAL);
    cudaFuncSetAttribute(gemm_pers<0, 1, 1, 0>, cudaFuncAttributeMaxDynamicSharedMemorySize, SM_TOTAL);
    cudaFuncSetAttribute(gemm_nsg, cudaFuncAttributeMaxDynamicSharedMemorySize, SM_TOTAL);

    // Pre-split weights + CSR build (once per launch)
    wconv_kernel<<<(WSLOTS * 16384 + 255) / 256, 256>>>(lw2, sw, nw, gw1, gw2);
    k_zero_cnt<<<SCAN_BLOCKS, 256>>>();
    k_count<<<(EE + 255) / 256, 256>>>(ei);
    k_blocksum<<<SCAN_BLOCKS, 256>>>();
    k_scan_bsum<<<1, 512>>>();
    k_rowstart<<<SCAN_BLOCKS, 256>>>();
    k_fill<<<(EE + 255) / 256, 256>>>(ei, ev);

    // Lift: hidden (split) -> h (fp32)
    lift_hidden_kernel<<<(NN * CC + 255) / 256, 256>>>(x, lw1, lb1);
    gemm_pers<0, 0, 1, 0><<<PGRID, 256, SM_TOTAL>>>(uh, ul, wbh, wbl, lb2,
                                                    nullptr, h, nullptr, nullptr);

    for (int l = 0; l < 2; l++) {
        const __nv_bfloat16* nh   = wbh + (size_t)(1 + 5 * l) * 16384;
        const __nv_bfloat16* nl   = wbl + (size_t)(1 + 5 * l) * 16384;
        const __nv_bfloat16* sh_  = wbh + (size_t)(2 + 5 * l) * 16384;
        const __nv_bfloat16* sl_  = wbl + (size_t)(2 + 5 * l) * 16384;
        const __nv_bfloat16* g1ah = wbh + (size_t)(3 + 5 * l) * 16384;
        const __nv_bfloat16* g1al = wbl + (size_t)(3 + 5 * l) * 16384;
        const __nv_bfloat16* g1bh = wbh + (size_t)(4 + 5 * l) * 16384;
        const __nv_bfloat16* g1bl = wbl + (size_t)(4 + 5 * l) * 16384;
        const __nv_bfloat16* g2h  = wbh + (size_t)(5 + 5 * l) * 16384;
        const __nv_bfloat16* g2l  = wbl + (size_t)(5 + 5 * l) * 16384;

        // fused: nb -> g_nb, self_f -> smem, tmp = self_f@W1a + bg1 -> g_tmp
        gemm_nsg<<<NTILES, 256, SM_TOTAL>>>(h, nh, nl, nbw + l * CC, nbuf,
                                            sh_, sl_, sb + l * CC,
                                            g1ah, g1al, gb1 + l * CC, tmp);
        // aggr (split) = pull-gather of neighbor
        k_aggr<<<(NN + 7) / 8, 256>>>();
        // u = gelu(aggr @ W1b + tmp)  (split)
        gemm_pers<1, 2, 0, 1><<<PGRID, 256, SM_TOTAL>>>(agh, agl, g1bh, g1bl,
                                                        zero, tmp,
                                                        nullptr, uh, ul);
        // h = h + u @ Wg2 + bg2  (fp32)
        gemm_pers<0, 1, 1, 0><<<PGRID, 256, SM_TOTAL>>>(uh, ul, g2h, g2l,
                                                        gb2 + l * CC, h,
                                                        h, nullptr, nullptr);
    }

    ln_kernel<<<(NN + 7) / 8, 256>>>(h, ng, nbt, out);
}

// round 9
// speedup vs baseline: 1.1707x; 1.0710x over previous
#include <cuda_runtime.h>
#include <cuda_bf16.h>
#include <math.h>
#include <stdint.h>

#define NN 100000
#define EE 1600000
#define CC 128
#define NTILES ((NN + 127) / 128)       // 782
#define PGRID 148
#define SCAN_BLOCKS ((NN + 255) / 256)  // 391

// ---------------------------------------------------------------------------
// Scratch (allocation-free rule: __device__ globals)
// ---------------------------------------------------------------------------
__device__ float g_h[(size_t)NN * CC];     // fp32 h (gather source + resid + LN)
__device__ float g_tmp[(size_t)NN * CC];   // fp32 (self@W1a + bg1)

__device__ __nv_bfloat16 g_uh[(size_t)NN * CC],  g_ul[(size_t)NN * CC];   // lift-hidden / u
__device__ __nv_bfloat16 g_agh[(size_t)NN * CC], g_agl[(size_t)NN * CC];  // gathered h

__device__ float g_sev[NN];                // per-row sum of edge values
__device__ float g_wnb[2 * 16384];         // Wn @ W1b (fp32, per layer)
__device__ float g_bnb[2 * CC];            // bn @ W1b
__device__ float g_zero[CC];               // zero bias

// CSR scratch
__device__ int   g_cnt[NN];
__device__ int   g_rowstart[NN + 1];
__device__ int   g_cursor[NN];
__device__ int   g_bsum[SCAN_BLOCKS];
__device__ int   g_boff[SCAN_BLOCKS];
__device__ int   g_ecol[EE];
__device__ float g_eval[EE];

// Pre-converted bf16 weight tiles (hi/lo split), layout [slot][n][k]
// slots: [0]=lift2; per layer l: [1+5l]=unused, [2+5l]=self,
// [3+5l]=Wnb (combined), [4+5l]=gate1a(k<128), [5+5l]=gate2.
#define WSLOTS 11
__device__ __nv_bfloat16 g_wbh[(size_t)WSLOTS * 16384];
__device__ __nv_bfloat16 g_wbl[(size_t)WSLOTS * 16384];

__device__ __forceinline__ float gelu_f(float v) {
    return 0.5f * v * (1.0f + erff(v * 0.7071067811865475f));
}
__device__ __forceinline__ void split_bf16(float v, __nv_bfloat16& hi, __nv_bfloat16& lo) {
    hi = __float2bfloat16(v);
    lo = __float2bfloat16(v - __bfloat162float(hi));
}

// ---------------------------------------------------------------------------
// mma.sync / cp.async helpers
// ---------------------------------------------------------------------------
__device__ __forceinline__ void ldsm_x4(uint32_t* r, uint32_t addr) {
    asm volatile("ldmatrix.sync.aligned.m8n8.x4.shared.b16 {%0,%1,%2,%3}, [%4];"
                 : "=r"(r[0]), "=r"(r[1]), "=r"(r[2]), "=r"(r[3]) : "r"(addr));
}
__device__ __forceinline__ void mma16816(float* d, const uint32_t* a, const uint32_t* b) {
    asm volatile(
        "mma.sync.aligned.m16n8k16.row.col.f32.bf16.bf16.f32 "
        "{%0,%1,%2,%3}, {%4,%5,%6,%7}, {%8,%9}, {%0,%1,%2,%3};"
        : "+f"(d[0]), "+f"(d[1]), "+f"(d[2]), "+f"(d[3])
        : "r"(a[0]), "r"(a[1]), "r"(a[2]), "r"(a[3]), "r"(b[0]), "r"(b[1]));
}
__device__ __forceinline__ void cp16(uint32_t dst, const void* src, int srcsize) {
    asm volatile("cp.async.cg.shared.global [%0], [%1], 16, %2;"
                 :: "r"(dst), "l"(src), "r"(srcsize) : "memory");
}
__device__ __forceinline__ void cp_commit() {
    asm volatile("cp.async.commit_group;" ::: "memory");
}
__device__ __forceinline__ void cp_wait_all() {
    asm volatile("cp.async.wait_group 0;" ::: "memory");
}

// ---------------------------------------------------------------------------
// Smem layout (6 tiles of 34816B)
// ---------------------------------------------------------------------------
#define ROWB 272
#define TILEB (128 * ROWB)          // 34816
#define SM_AH 0
#define SM_AL TILEB
#define SM_B0 (2 * TILEB)
#define SM_B1 (4 * TILEB)
#define SM_TOTAL (6 * TILEB)        // 208896

__device__ __forceinline__ void mma_chunk(float acc[2][8][4], uint32_t aH,
                                          uint32_t aL, uint32_t bH, uint32_t bL) {
#pragma unroll
    for (int ks = 0; ks < 8; ks++) {
        uint32_t ah[2][4], al[2][4], bh[4][4], bl[4][4];
        ldsm_x4(ah[0], aH + ks * 32);
        ldsm_x4(ah[1], aH + ks * 32 + 16 * ROWB);
        ldsm_x4(al[0], aL + ks * 32);
        ldsm_x4(al[1], aL + ks * 32 + 16 * ROWB);
#pragma unroll
        for (int np = 0; np < 4; np++) {
            ldsm_x4(bh[np], bH + ks * 32 + np * 16 * ROWB);
            ldsm_x4(bl[np], bL + ks * 32 + np * 16 * ROWB);
        }
#pragma unroll
        for (int mi = 0; mi < 2; mi++)
#pragma unroll
            for (int nt = 0; nt < 8; nt++) {
                uint32_t bbh[2] = { bh[nt >> 1][(nt & 1) * 2], bh[nt >> 1][(nt & 1) * 2 + 1] };
                uint32_t bbl[2] = { bl[nt >> 1][(nt & 1) * 2], bl[nt >> 1][(nt & 1) * 2 + 1] };
                mma16816(acc[mi][nt], ah[mi], bbh);
                mma16816(acc[mi][nt], ah[mi], bbl);
                mma16816(acc[mi][nt], al[mi], bbh);
            }
    }
}

#define ACC_ZERO(acc)                                   \
    _Pragma("unroll")                                   \
    for (int mi = 0; mi < 2; mi++)                      \
        _Pragma("unroll")                               \
        for (int nt = 0; nt < 8; nt++)                  \
            _Pragma("unroll")                           \
            for (int e = 0; e < 4; e++) acc[mi][nt][e] = 0.0f;

__device__ __forceinline__ void stage_A_f32(char* smem, const float* __restrict__ A,
                                            int m0, int tid) {
#pragma unroll
    for (int i = 0; i < 8; i++) {
        int ci = tid + i * 256;
        int row = ci >> 4, ch = ci & 15;
        int gm = m0 + row;
        float v[8];
        if (gm < NN) {
            float4 a = *(const float4*)(A + (size_t)gm * 128 + ch * 8);
            float4 b = *(const float4*)(A + (size_t)gm * 128 + ch * 8 + 4);
            v[0] = a.x; v[1] = a.y; v[2] = a.z; v[3] = a.w;
            v[4] = b.x; v[5] = b.y; v[6] = b.z; v[7] = b.w;
        } else {
#pragma unroll
            for (int e = 0; e < 8; e++) v[e] = 0.0f;
        }
        __align__(16) __nv_bfloat16 h8[8], l8[8];
#pragma unroll
        for (int e = 0; e < 8; e++) split_bf16(v[e], h8[e], l8[e]);
        uint32_t off = (uint32_t)(row * ROWB + ch * 16);
        *(uint4*)(smem + SM_AH + off) = *(uint4*)h8;
        *(uint4*)(smem + SM_AL + off) = *(uint4*)l8;
    }
}

__device__ __forceinline__ void stage_A_split(uint32_t abase,
                                              const __nv_bfloat16* __restrict__ Ah,
                                              const __nv_bfloat16* __restrict__ Al,
                                              int m0, int tid) {
#pragma unroll
    for (int i = 0; i < 8; i++) {
        int ci = tid + i * 256;
        int row = ci >> 4, ch = ci & 15;
        int gm = m0 + row;
        int ss = (gm < NN) ? 16 : 0;
        int gms = (gm < NN) ? gm : (NN - 1);
        uint32_t off = (uint32_t)(row * ROWB + ch * 16);
        cp16(abase + off, Ah + (size_t)gms * 128 + ch * 8, ss);
        cp16(abase + TILEB + off, Al + (size_t)gms * 128 + ch * 8, ss);
    }
}
__device__ __forceinline__ void stage_B(uint32_t bbase, const __nv_bfloat16* __restrict__ Bh,
                                        const __nv_bfloat16* __restrict__ Bl, int tid) {
#pragma unroll
    for (int i = 0; i < 8; i++) {
        int ci = tid + i * 256;
        int row = ci >> 4, ch = ci & 15;
        uint32_t off = (uint32_t)(row * ROWB + ch * 16);
        cp16(bbase + off, Bh + ci * 8, 16);
        cp16(bbase + TILEB + off, Bl + ci * 8, 16);
    }
}

__device__ __forceinline__ void epi_f32(float acc[2][8][4], const float* __restrict__ bias,
                                        float* __restrict__ Out, int m0,
                                        int warp_m, int warp_n, int lane) {
#pragma unroll
    for (int mi = 0; mi < 2; mi++) {
        int r0 = m0 + warp_m * 32 + mi * 16 + (lane >> 2);
#pragma unroll
        for (int half = 0; half < 2; half++) {
            int r = r0 + half * 8;
            if (r >= NN) continue;
#pragma unroll
            for (int nt = 0; nt < 8; nt++) {
                int col = warp_n * 64 + nt * 8 + (lane & 3) * 2;
                float x0 = acc[mi][nt][half * 2 + 0] + __ldg(bias + col);
                float x1 = acc[mi][nt][half * 2 + 1] + __ldg(bias + col + 1);
                *(float2*)(Out + (size_t)r * 128 + col) = make_float2(x0, x1);
            }
        }
    }
}

// ---------------------------------------------------------------------------
// Fused self+gate1a kernel (one A stage of h -> 2 MMA blocks):
//   sf  = h @ Ws + bs    -> SMEM (split, replaces h in A slot)
//   tmp = sf @ Wg1a + bg1 -> g_tmp (fp32)
// ---------------------------------------------------------------------------
__global__ void __launch_bounds__(256, 1) gemm_sg(
    const float* __restrict__ H,
    const __nv_bfloat16* __restrict__ Bsh, const __nv_bfloat16* __restrict__ Bsl,
    const float* __restrict__ bs,
    const __nv_bfloat16* __restrict__ Bgh, const __nv_bfloat16* __restrict__ Bgl,
    const float* __restrict__ bg, float* __restrict__ OutT) {
    extern __shared__ __align__(16) char smem[];
    const uint32_t sb = (uint32_t)__cvta_generic_to_shared(smem);
    const int tid = threadIdx.x;
    const int lane = tid & 31;
    const int warp_m = (tid >> 5) >> 1;
    const int warp_n = (tid >> 5) & 1;
    const int m0 = blockIdx.x * 128;

    const uint32_t a_lane = (uint32_t)(((lane & 7) + ((lane >> 3) & 1) * 8) * ROWB +
                                       (lane >> 4) * 16) +
                            (uint32_t)(warp_m * 32 * ROWB);
    const uint32_t b_lane = (uint32_t)(((lane & 7) + ((lane >> 4) & 1) * 8) * ROWB +
                                       ((lane >> 3) & 1) * 16) +
                            (uint32_t)(warp_n * 64 * ROWB);

    stage_B(sb + SM_B0, Bsh, Bsl, tid);
    cp_commit();
    stage_A_f32(smem, H, m0, tid);
    cp_wait_all();
    __syncthreads();

    // prefetch gate1a weights during self MMA
    stage_B(sb + SM_B1, Bgh, Bgl, tid);
    cp_commit();

    float acc[2][8][4];
    ACC_ZERO(acc);
    mma_chunk(acc, sb + SM_AH + a_lane, sb + SM_AL + a_lane,
              sb + SM_B0 + b_lane, sb + SM_B0 + TILEB + b_lane);
    __syncthreads();                 // all warps done reading A (h)

    // write self_f (+bs) split into SMEM A slot
#pragma unroll
    for (int mi = 0; mi < 2; mi++) {
#pragma unroll
        for (int half = 0; half < 2; half++) {
            int row = warp_m * 32 + mi * 16 + (lane >> 2) + half * 8;
#pragma unroll
            for (int nt = 0; nt < 8; nt++) {
                int col = warp_n * 64 + nt * 8 + (lane & 3) * 2;
                float x0 = acc[mi][nt][half * 2 + 0] + __ldg(bs + col);
                float x1 = acc[mi][nt][half * 2 + 1] + __ldg(bs + col + 1);
                __nv_bfloat16 h0, l0, h1, l1;
                split_bf16(x0, h0, l0);
                split_bf16(x1, h1, l1);
                uint32_t off = (uint32_t)(row * ROWB + col * 2);
                *(__nv_bfloat162*)(smem + SM_AH + off) = __nv_bfloat162(h0, h1);
                *(__nv_bfloat162*)(smem + SM_AL + off) = __nv_bfloat162(l0, l1);
            }
        }
    }
    cp_wait_all();
    __syncthreads();                 // self_f visible + B_g1a ready

    ACC_ZERO(acc);
    mma_chunk(acc, sb + SM_AH + a_lane, sb + SM_AL + a_lane,
              sb + SM_B1 + b_lane, sb + SM_B1 + TILEB + b_lane);
    epi_f32(acc, bg, OutT, m0, warp_m, warp_n, lane);
}

// ---------------------------------------------------------------------------
// Persistent GEMM. RESID: 0 none, 1 post-act, 2 pre-act.
// SCV: add sev[r]*cvec[col] pre-activation.
// ---------------------------------------------------------------------------
template <int GELU, int RESID, int WF32, int WSPLIT, int SCV>
__global__ void __launch_bounds__(256, 1) gemm_pers(
    const __nv_bfloat16* __restrict__ Ah, const __nv_bfloat16* __restrict__ Al,
    const __nv_bfloat16* __restrict__ Bh, const __nv_bfloat16* __restrict__ Bl,
    const float* __restrict__ bias, const float* __restrict__ R,
    const float* __restrict__ sev, const float* __restrict__ cvec,
    float* __restrict__ OutF, __nv_bfloat16* __restrict__ OutH,
    __nv_bfloat16* __restrict__ OutL) {
    extern __shared__ __align__(16) char smem[];
    const uint32_t sb = (uint32_t)__cvta_generic_to_shared(smem);
    const int tid = threadIdx.x;
    const int lane = tid & 31;
    const int warp_m = (tid >> 5) >> 1;
    const int warp_n = (tid >> 5) & 1;

    const uint32_t a_lane = (uint32_t)(((lane & 7) + ((lane >> 3) & 1) * 8) * ROWB +
                                       (lane >> 4) * 16) +
                            (uint32_t)(warp_m * 32 * ROWB);
    const uint32_t b_lane = (uint32_t)(((lane & 7) + ((lane >> 4) & 1) * 8) * ROWB +
                                       ((lane >> 3) & 1) * 16) +
                            (uint32_t)(warp_n * 64 * ROWB);
    const uint32_t bH = sb + SM_B0 + b_lane;
    const uint32_t bL = sb + SM_B0 + TILEB + b_lane;

    float b0[8], b1[8], cv0[8], cv1[8];
#pragma unroll
    for (int nt = 0; nt < 8; nt++) {
        int col = warp_n * 64 + nt * 8 + (lane & 3) * 2;
        b0[nt] = __ldg(bias + col);
        b1[nt] = __ldg(bias + col + 1);
        if (SCV) {
            cv0[nt] = __ldg(cvec + col);
            cv1[nt] = __ldg(cvec + col + 1);
        }
    }

    stage_B(sb + SM_B0, Bh, Bl, tid);
    int tile = blockIdx.x;
    if (tile < NTILES) stage_A_split(sb + SM_AH, Ah, Al, tile * 128, tid);
    cp_commit();
    cp_wait_all();
    __syncthreads();

    int buf = 0;
    for (; tile < NTILES; tile += PGRID) {
        const int m0 = tile * 128;
        const int nxt = tile + PGRID;
        if (nxt < NTILES)
            stage_A_split(sb + (buf ? SM_AH : SM_B1), Ah, Al, nxt * 128, tid);
        cp_commit();

        float acc[2][8][4];
        ACC_ZERO(acc);
        const uint32_t aB = sb + (buf ? SM_B1 : SM_AH);
        mma_chunk(acc, aB + a_lane, aB + TILEB + a_lane, bH, bL);

#pragma unroll
        for (int mi = 0; mi < 2; mi++) {
            int r0 = m0 + warp_m * 32 + mi * 16 + (lane >> 2);
#pragma unroll
            for (int half = 0; half < 2; half++) {
                int r = r0 + half * 8;
                if (r >= NN) continue;
                const float* rrow = RESID ? (R + (size_t)r * 128) : nullptr;
                float sv = SCV ? __ldg(sev + r) : 0.0f;
#pragma unroll
                for (int nt = 0; nt < 8; nt++) {
                    int col = warp_n * 64 + nt * 8 + (lane & 3) * 2;
                    float x0 = acc[mi][nt][half * 2 + 0] + b0[nt];
                    float x1 = acc[mi][nt][half * 2 + 1] + b1[nt];
                    if (SCV) { x0 = fmaf(sv, cv0[nt], x0); x1 = fmaf(sv, cv1[nt], x1); }
                    float2 rr;
                    if (RESID) rr = *(const float2*)(rrow + col);
                    if (RESID == 2) { x0 += rr.x; x1 += rr.y; }
                    if (GELU) { x0 = gelu_f(x0); x1 = gelu_f(x1); }
                    if (RESID == 1) { x0 += rr.x; x1 += rr.y; }
                    if (WF32)
                        *(float2*)(OutF + (size_t)r * 128 + col) = make_float2(x0, x1);
                    if (WSPLIT) {
                        __nv_bfloat16 h0, l0, h1, l1;
                        split_bf16(x0, h0, l0);
                        split_bf16(x1, h1, l1);
                        *(__nv_bfloat162*)(OutH + (size_t)r * 128 + col) =
                            __nv_bfloat162(h0, h1);
                        *(__nv_bfloat162*)(OutL + (size_t)r * 128 + col) =
                            __nv_bfloat162(l0, l1);
                    }
                }
            }
        }
        cp_wait_all();
        __syncthreads();
        buf ^= 1;
    }
}

// ---------------------------------------------------------------------------
// Combined weights: Wnb = Wn @ W1b (fp32), bnb = bn @ W1b
// ---------------------------------------------------------------------------
__global__ void k_wcomb(const float* __restrict__ nw, const float* __restrict__ gw1) {
    int idx = blockIdx.x * blockDim.x + threadIdx.x;
    if (idx >= 2 * 16384) return;
    int l = idx >> 14;
    int k = (idx >> 7) & 127;
    int n = idx & 127;
    const float* a = nw + (size_t)l * 16384 + k * 128;
    const float* b = gw1 + (size_t)l * 32768 + 16384 + n;
    float s = 0.0f;
#pragma unroll 8
    for (int m = 0; m < 128; m++) s = fmaf(a[m], b[(size_t)m * 128], s);
    g_wnb[idx] = s;
}
__global__ void k_bnb(const float* __restrict__ nbw, const float* __restrict__ gw1) {
    int idx = blockIdx.x * blockDim.x + threadIdx.x;
    if (idx >= 2 * CC) return;
    int l = idx >> 7, n = idx & 127;
    float s = 0.0f;
#pragma unroll 8
    for (int m = 0; m < 128; m++)
        s = fmaf(nbw[l * 128 + m], gw1[(size_t)l * 32768 + 16384 + (size_t)m * 128 + n], s);
    g_bnb[idx] = s;
}

// ---------------------------------------------------------------------------
// Weight conversion: fp32 W[K,N] -> bf16 hi/lo B[N,K]
// ---------------------------------------------------------------------------
__global__ void wconv_kernel(const float* __restrict__ lw2,
                             const float* __restrict__ sw,
                             const float* __restrict__ nw,
                             const float* __restrict__ gw1,
                             const float* __restrict__ gw2) {
    int idx = blockIdx.x * blockDim.x + threadIdx.x;
    if (idx >= WSLOTS * 16384) return;
    int slot = idx >> 14;
    int within = idx & 16383;
    int n = within >> 7;
    int k = within & 127;
    const float* src;
    if (slot == 0) {
        src = lw2 + k * 128 + n;
    } else {
        int l = (slot - 1) / 5, j = (slot - 1) % 5;
        if (j == 0)      src = nw  + (size_t)l * 16384 + k * 128 + n;      // unused
        else if (j == 1) src = sw  + (size_t)l * 16384 + k * 128 + n;      // self
        else if (j == 2) src = g_wnb + (size_t)l * 16384 + k * 128 + n;    // Wnb
        else if (j == 3) src = gw1 + (size_t)l * 32768 + k * 128 + n;      // gate1a
        else             src = gw2 + (size_t)l * 16384 + k * 128 + n;      // gate2
    }
    __nv_bfloat16 hi, lo;
    split_bf16(*src, hi, lo);
    g_wbh[idx] = hi;
    g_wbl[idx] = lo;
}

// ---------------------------------------------------------------------------
// CSR build
// ---------------------------------------------------------------------------
__global__ void k_zero_cnt() {
    int i = blockIdx.x * blockDim.x + threadIdx.x;
    if (i < NN) g_cnt[i] = 0;
}
__global__ void k_count(const int* __restrict__ ei) {
    int e = blockIdx.x * blockDim.x + threadIdx.x;
    if (e < EE) atomicAdd(&g_cnt[ei[e]], 1);
}
__global__ void k_blocksum() {
    __shared__ int sh[256];
    int i = blockIdx.x * 256 + threadIdx.x;
    int v = (i < NN) ? g_cnt[i] : 0;
    sh[threadIdx.x] = v;
    __syncthreads();
    for (int s = 128; s; s >>= 1) {
        if (threadIdx.x < s) sh[threadIdx.x] += sh[threadIdx.x + s];
        __syncthreads();
    }
    if (threadIdx.x == 0) g_bsum[blockIdx.x] = sh[0];
}
__global__ void k_scan_bsum() {
    __shared__ int sh[512];
    int t = threadIdx.x;
    sh[t] = (t < SCAN_BLOCKS) ? g_bsum[t] : 0;
    __syncthreads();
    for (int off = 1; off < 512; off <<= 1) {
        int v = (t >= off) ? sh[t - off] : 0;
        __syncthreads();
        sh[t] += v;
        __syncthreads();
    }
    if (t < SCAN_BLOCKS) g_boff[t] = sh[t] - g_bsum[t];
}
__global__ void k_rowstart() {
    __shared__ int sh[256];
    int i = blockIdx.x * 256 + threadIdx.x;
    int v = (i < NN) ? g_cnt[i] : 0;
    sh[threadIdx.x] = v;
    __syncthreads();
    for (int off = 1; off < 256; off <<= 1) {
        int u = (threadIdx.x >= off) ? sh[threadIdx.x - off] : 0;
        __syncthreads();
        sh[threadIdx.x] += u;
        __syncthreads();
    }
    if (i < NN) {
        int excl = sh[threadIdx.x] - v + g_boff[blockIdx.x];
        g_rowstart[i] = excl;
        g_cursor[i] = excl;
        if (i == NN - 1) g_rowstart[NN] = excl + v;
    }
}
__global__ void k_fill(const int* __restrict__ ei, const float* __restrict__ ev) {
    int e = blockIdx.x * blockDim.x + threadIdx.x;
    if (e >= EE) return;
    int row = ei[e];
    int pos = atomicAdd(&g_cursor[row], 1);
    g_ecol[pos] = ei[EE + e];
    g_eval[pos] = ev[e];
}

// ---------------------------------------------------------------------------
// Pull aggregation of h: gh[r] = sum ev*h[col]; also sev[r] = sum ev.
// ---------------------------------------------------------------------------
__global__ void k_aggr() {
    int r = blockIdx.x * 8 + (threadIdx.x >> 5);
    if (r >= NN) return;
    int lane = threadIdx.x & 31;
    int s = g_rowstart[r];
    int e = g_rowstart[r + 1];
    float acc[4] = {0.f, 0.f, 0.f, 0.f};
    float sev = 0.f;
    for (int j = s; j < e; j++) {
        int c = __ldg(&g_ecol[j]);
        float v = __ldg(&g_eval[j]);
        sev += v;
        const float* srow = g_h + (size_t)c * CC + lane;
        acc[0] = fmaf(__ldg(srow),      v, acc[0]);
        acc[1] = fmaf(__ldg(srow + 32), v, acc[1]);
        acc[2] = fmaf(__ldg(srow + 64), v, acc[2]);
        acc[3] = fmaf(__ldg(srow + 96), v, acc[3]);
    }
#pragma unroll
    for (int i = 0; i < 4; i++) {
        __nv_bfloat16 hi, lo;
        split_bf16(acc[i], hi, lo);
        g_agh[(size_t)r * CC + lane + i * 32] = hi;
        g_agl[(size_t)r * CC + lane + i * 32] = lo;
    }
    if (lane == 0) g_sev[r] = sev;
}

// ---------------------------------------------------------------------------
// Lift stage 1 + LayerNorm
// ---------------------------------------------------------------------------
__global__ void lift_hidden_kernel(const float* __restrict__ x,
                                   const float* __restrict__ w1,
                                   const float* __restrict__ b1) {
    int idx = blockIdx.x * blockDim.x + threadIdx.x;
    if (idx >= NN * CC) return;
    int n = idx >> 7;
    int c = idx & 127;
    const float* xr = x + (size_t)n * 9 + 3;
    float acc = b1[c];
#pragma unroll
    for (int i = 0; i < 6; i++)
        acc = fmaf(xr[i], w1[i * CC + c], acc);
    float v = gelu_f(acc);
    __nv_bfloat16 hi, lo;
    split_bf16(v, hi, lo);
    g_uh[idx] = hi;
    g_ul[idx] = lo;
}

__global__ void ln_kernel(const float* __restrict__ h,
                          const float* __restrict__ g,
                          const float* __restrict__ b,
                          float* __restrict__ out) {
    int n = blockIdx.x * 8 + (threadIdx.x >> 5);
    if (n >= NN) return;
    int lane = threadIdx.x & 31;
    const float* r = h + (size_t)n * CC;
    float v[4];
    float s = 0.f;
#pragma unroll
    for (int i = 0; i < 4; i++) { v[i] = r[lane + i * 32]; s += v[i]; }
#pragma unroll
    for (int o = 16; o; o >>= 1) s += __shfl_xor_sync(0xffffffffu, s, o);
    float mu = s * (1.f / 128.f);
    float q = 0.f;
#pragma unroll
    for (int i = 0; i < 4; i++) { float d = v[i] - mu; q = fmaf(d, d, q); }
#pragma unroll
    for (int o = 16; o; o >>= 1) q += __shfl_xor_sync(0xffffffffu, q, o);
    float inv = rsqrtf(q * (1.f / 128.f) + 1e-5f);
#pragma unroll
    for (int i = 0; i < 4; i++) {
        int c = lane + i * 32;
        out[(size_t)n * CC + c] = fmaf((v[i] - mu) * inv, g[c], b[c]);
    }
}

// ---------------------------------------------------------------------------
extern "C" void kernel_launch(void* const* d_in, const int* in_sizes, int n_in,
                              void* d_out, int out_size) {
    const float* x   = (const float*)d_in[0];
    const int*   ei  = (const int*)d_in[1];
    const float* ev  = (const float*)d_in[2];
    const float* lw1 = (const float*)d_in[3];
    const float* lb1 = (const float*)d_in[4];
    const float* lw2 = (const float*)d_in[5];
    const float* lb2 = (const float*)d_in[6];
    const float* sw  = (const float*)d_in[7];
    const float* sb  = (const float*)d_in[8];
    const float* nw  = (const float*)d_in[9];
    const float* nbw = (const float*)d_in[10];
    const float* gw1 = (const float*)d_in[11];
    const float* gb1 = (const float*)d_in[12];
    const float* gw2 = (const float*)d_in[13];
    const float* gb2 = (const float*)d_in[14];
    const float* ng  = (const float*)d_in[15];
    const float* nbt = (const float*)d_in[16];
    float* out = (float*)d_out;

    float *h, *tmp, *zero, *sev, *bnb;
    cudaGetSymbolAddress((void**)&h, g_h);
    cudaGetSymbolAddress((void**)&tmp, g_tmp);
    cudaGetSymbolAddress((void**)&zero, g_zero);
    cudaGetSymbolAddress((void**)&sev, g_sev);
    cudaGetSymbolAddress((void**)&bnb, g_bnb);
    __nv_bfloat16 *wbh, *wbl, *uh, *ul, *agh, *agl;
    cudaGetSymbolAddress((void**)&wbh, g_wbh);
    cudaGetSymbolAddress((void**)&wbl, g_wbl);
    cudaGetSymbolAddress((void**)&uh, g_uh);
    cudaGetSymbolAddress((void**)&ul, g_ul);
    cudaGetSymbolAddress((void**)&agh, g_agh);
    cudaGetSymbolAddress((void**)&agl, g_agl);

    cudaFuncSetAttribute(gemm_pers<0, 0, 1, 0, 0>, cudaFuncAttributeMaxDynamicSharedMemorySize, SM_TOTAL);
    cudaFuncSetAttribute(gemm_pers<1, 2, 0, 1, 1>, cudaFuncAttributeMaxDynamicSharedMemorySize, SM_TOTAL);
    cudaFuncSetAttribute(gemm_pers<0, 1, 1, 0, 0>, cudaFuncAttributeMaxDynamicSharedMemorySize, SM_TOTAL);
    cudaFuncSetAttribute(gemm_sg, cudaFuncAttributeMaxDynamicSharedMemorySize, SM_TOTAL);

    // Combined weights, splits, CSR (once per launch)
    k_wcomb<<<(2 * 16384 + 255) / 256, 256>>>(nw, gw1);
    k_bnb<<<1, 256>>>(nbw, gw1);
    wconv_kernel<<<(WSLOTS * 16384 + 255) / 256, 256>>>(lw2, sw, nw, gw1, gw2);
    k_zero_cnt<<<SCAN_BLOCKS, 256>>>();
    k_count<<<(EE + 255) / 256, 256>>>(ei);
    k_blocksum<<<SCAN_BLOCKS, 256>>>();
    k_scan_bsum<<<1, 512>>>();
    k_rowstart<<<SCAN_BLOCKS, 256>>>();
    k_fill<<<(EE + 255) / 256, 256>>>(ei, ev);

    // Lift
    lift_hidden_kernel<<<(NN * CC + 255) / 256, 256>>>(x, lw1, lb1);
    gemm_pers<0, 0, 1, 0, 0><<<PGRID, 256, SM_TOTAL>>>(uh, ul, wbh, wbl, lb2,
                                                       nullptr, nullptr, nullptr,
                                                       h, nullptr, nullptr);

    for (int l = 0; l < 2; l++) {
        const __nv_bfloat16* sh_  = wbh + (size_t)(2 + 5 * l) * 16384;
        const __nv_bfloat16* sl_  = wbl + (size_t)(2 + 5 * l) * 16384;
        const __nv_bfloat16* wnbh = wbh + (size_t)(3 + 5 * l) * 16384;
        const __nv_bfloat16* wnbl = wbl + (size_t)(3 + 5 * l) * 16384;
        const __nv_bfloat16* g1ah = wbh + (size_t)(4 + 5 * l) * 16384;
        const __nv_bfloat16* g1al = wbl + (size_t)(4 + 5 * l) * 16384;
        const __nv_bfloat16* g2h  = wbh + (size_t)(5 + 5 * l) * 16384;
        const __nv_bfloat16* g2l  = wbl + (size_t)(5 + 5 * l) * 16384;

        // gh (split) + sev = pull-gather of h
        k_aggr<<<(NN + 7) / 8, 256>>>();
        // fused: self_f -> smem, tmp = self_f@W1a + bg1 -> g_tmp
        gemm_sg<<<NTILES, 256, SM_TOTAL>>>(h, sh_, sl_, sb + l * CC,
                                           g1ah, g1al, gb1 + l * CC, tmp);
        // u = gelu(gh@Wnb + tmp + sev*bnb)  (split)
        gemm_pers<1, 2, 0, 1, 1><<<PGRID, 256, SM_TOTAL>>>(agh, agl, wnbh, wnbl,
                                                           zero, tmp, sev,
                                                           bnb + l * CC,
                                                           nullptr, uh, ul);
        // h = h + u @ Wg2 + bg2  (fp32)
        gemm_pers<0, 1, 1, 0, 0><<<PGRID, 256, SM_TOTAL>>>(uh, ul, g2h, g2l,
                                                           gb2 + l * CC, h,
                                                           nullptr, nullptr,
                                                           h, nullptr, nullptr);
    }

    ln_kernel<<<(NN + 7) / 8, 256>>>(h, ng, nbt, out);
}

// round 10
// speedup vs baseline: 1.2277x; 1.0488x over previous
#include <cuda_runtime.h>
#include <cuda_bf16.h>
#include <math.h>
#include <stdint.h>

#define NN 100000
#define EE 1600000
#define CC 128
#define NTILES ((NN + 127) / 128)       // 782
#define PGRID 148
#define SCAN_BLOCKS ((NN + 255) / 256)  // 391

// ---------------------------------------------------------------------------
// Scratch (allocation-free rule: __device__ globals)
// ---------------------------------------------------------------------------
__device__ float g_h[(size_t)NN * CC];     // fp32 h (gather source + resid + LN)
__device__ float g_tmp[(size_t)NN * CC];   // fp32 (h@Wsg + bsg)

__device__ __nv_bfloat16 g_uh[(size_t)NN * CC],  g_ul[(size_t)NN * CC];   // lift-hidden / u
__device__ __nv_bfloat16 g_hh[(size_t)NN * CC],  g_hl[(size_t)NN * CC];   // h split
__device__ __nv_bfloat16 g_agh[(size_t)NN * CC], g_agl[(size_t)NN * CC];  // gathered h

__device__ float g_sev[NN];                // per-row sum of edge values
__device__ float g_wnb[2 * 16384];         // Wn @ W1b (fp32)
__device__ float g_wsg[2 * 16384];         // Ws @ W1a (fp32)
__device__ float g_bnb[2 * CC];            // bn @ W1b
__device__ float g_bsg[2 * CC];            // bs @ W1a + bg1
__device__ float g_zero[CC];               // zero bias

// CSR scratch
__device__ int   g_cnt[NN];
__device__ int   g_rowstart[NN + 1];
__device__ int   g_cursor[NN];
__device__ int   g_bsum[SCAN_BLOCKS];
__device__ int   g_boff[SCAN_BLOCKS];
__device__ int   g_ecol[EE];
__device__ float g_eval[EE];

// Pre-converted bf16 weight tiles (hi/lo split), layout [slot][n][k]
// slots: [0]=lift2; per layer l: [1+3l]=Wsg, [2+3l]=Wnb, [3+3l]=gate2.
#define WSLOTS 7
__device__ __nv_bfloat16 g_wbh[(size_t)WSLOTS * 16384];
__device__ __nv_bfloat16 g_wbl[(size_t)WSLOTS * 16384];

__device__ __forceinline__ float gelu_f(float v) {
    return 0.5f * v * (1.0f + erff(v * 0.7071067811865475f));
}
__device__ __forceinline__ void split_bf16(float v, __nv_bfloat16& hi, __nv_bfloat16& lo) {
    hi = __float2bfloat16(v);
    lo = __float2bfloat16(v - __bfloat162float(hi));
}

// ---------------------------------------------------------------------------
// mma.sync / cp.async helpers
// ---------------------------------------------------------------------------
__device__ __forceinline__ void ldsm_x4(uint32_t* r, uint32_t addr) {
    asm volatile("ldmatrix.sync.aligned.m8n8.x4.shared.b16 {%0,%1,%2,%3}, [%4];"
                 : "=r"(r[0]), "=r"(r[1]), "=r"(r[2]), "=r"(r[3]) : "r"(addr));
}
__device__ __forceinline__ void mma16816(float* d, const uint32_t* a, const uint32_t* b) {
    asm volatile(
        "mma.sync.aligned.m16n8k16.row.col.f32.bf16.bf16.f32 "
        "{%0,%1,%2,%3}, {%4,%5,%6,%7}, {%8,%9}, {%0,%1,%2,%3};"
        : "+f"(d[0]), "+f"(d[1]), "+f"(d[2]), "+f"(d[3])
        : "r"(a[0]), "r"(a[1]), "r"(a[2]), "r"(a[3]), "r"(b[0]), "r"(b[1]));
}
__device__ __forceinline__ void cp16(uint32_t dst, const void* src, int srcsize) {
    asm volatile("cp.async.cg.shared.global [%0], [%1], 16, %2;"
                 :: "r"(dst), "l"(src), "r"(srcsize) : "memory");
}
__device__ __forceinline__ void cp_commit() {
    asm volatile("cp.async.commit_group;" ::: "memory");
}
__device__ __forceinline__ void cp_wait_all() {
    asm volatile("cp.async.wait_group 0;" ::: "memory");
}

// ---------------------------------------------------------------------------
// Smem layout (6 tiles of 34816B)
// ---------------------------------------------------------------------------
#define ROWB 272
#define TILEB (128 * ROWB)          // 34816
#define SM_AH 0
#define SM_AL TILEB
#define SM_B0 (2 * TILEB)
#define SM_B1 (4 * TILEB)
#define SM_TOTAL (6 * TILEB)        // 208896

__device__ __forceinline__ void mma_chunk(float acc[2][8][4], uint32_t aH,
                                          uint32_t aL, uint32_t bH, uint32_t bL) {
#pragma unroll
    for (int ks = 0; ks < 8; ks++) {
        uint32_t ah[2][4], al[2][4], bh[4][4], bl[4][4];
        ldsm_x4(ah[0], aH + ks * 32);
        ldsm_x4(ah[1], aH + ks * 32 + 16 * ROWB);
        ldsm_x4(al[0], aL + ks * 32);
        ldsm_x4(al[1], aL + ks * 32 + 16 * ROWB);
#pragma unroll
        for (int np = 0; np < 4; np++) {
            ldsm_x4(bh[np], bH + ks * 32 + np * 16 * ROWB);
            ldsm_x4(bl[np], bL + ks * 32 + np * 16 * ROWB);
        }
#pragma unroll
        for (int mi = 0; mi < 2; mi++)
#pragma unroll
            for (int nt = 0; nt < 8; nt++) {
                uint32_t bbh[2] = { bh[nt >> 1][(nt & 1) * 2], bh[nt >> 1][(nt & 1) * 2 + 1] };
                uint32_t bbl[2] = { bl[nt >> 1][(nt & 1) * 2], bl[nt >> 1][(nt & 1) * 2 + 1] };
                mma16816(acc[mi][nt], ah[mi], bbh);
                mma16816(acc[mi][nt], ah[mi], bbl);
                mma16816(acc[mi][nt], al[mi], bbh);
            }
    }
}

#define ACC_ZERO(acc)                                   \
    _Pragma("unroll")                                   \
    for (int mi = 0; mi < 2; mi++)                      \
        _Pragma("unroll")                               \
        for (int nt = 0; nt < 8; nt++)                  \
            _Pragma("unroll")                           \
            for (int e = 0; e < 4; e++) acc[mi][nt][e] = 0.0f;

__device__ __forceinline__ void stage_A_split(uint32_t abase,
                                              const __nv_bfloat16* __restrict__ Ah,
                                              const __nv_bfloat16* __restrict__ Al,
                                              int m0, int tid) {
#pragma unroll
    for (int i = 0; i < 8; i++) {
        int ci = tid + i * 256;
        int row = ci >> 4, ch = ci & 15;
        int gm = m0 + row;
        int ss = (gm < NN) ? 16 : 0;
        int gms = (gm < NN) ? gm : (NN - 1);
        uint32_t off = (uint32_t)(row * ROWB + ch * 16);
        cp16(abase + off, Ah + (size_t)gms * 128 + ch * 8, ss);
        cp16(abase + TILEB + off, Al + (size_t)gms * 128 + ch * 8, ss);
    }
}
__device__ __forceinline__ void stage_B(uint32_t bbase, const __nv_bfloat16* __restrict__ Bh,
                                        const __nv_bfloat16* __restrict__ Bl, int tid) {
#pragma unroll
    for (int i = 0; i < 8; i++) {
        int ci = tid + i * 256;
        int row = ci >> 4, ch = ci & 15;
        uint32_t off = (uint32_t)(row * ROWB + ch * 16);
        cp16(bbase + off, Bh + ci * 8, 16);
        cp16(bbase + TILEB + off, Bl + ci * 8, 16);
    }
}

// ---------------------------------------------------------------------------
// Persistent GEMM. RESID: 0 none, 1 post-act, 2 pre-act.
// SCV: add sev[r]*cvec[col] pre-activation.
// ---------------------------------------------------------------------------
template <int GELU, int RESID, int WF32, int WSPLIT, int SCV>
__global__ void __launch_bounds__(256, 1) gemm_pers(
    const __nv_bfloat16* __restrict__ Ah, const __nv_bfloat16* __restrict__ Al,
    const __nv_bfloat16* __restrict__ Bh, const __nv_bfloat16* __restrict__ Bl,
    const float* __restrict__ bias, const float* __restrict__ R,
    const float* __restrict__ sev, const float* __restrict__ cvec,
    float* __restrict__ OutF, __nv_bfloat16* __restrict__ OutH,
    __nv_bfloat16* __restrict__ OutL) {
    extern __shared__ __align__(16) char smem[];
    const uint32_t sb = (uint32_t)__cvta_generic_to_shared(smem);
    const int tid = threadIdx.x;
    const int lane = tid & 31;
    const int warp_m = (tid >> 5) >> 1;
    const int warp_n = (tid >> 5) & 1;

    const uint32_t a_lane = (uint32_t)(((lane & 7) + ((lane >> 3) & 1) * 8) * ROWB +
                                       (lane >> 4) * 16) +
                            (uint32_t)(warp_m * 32 * ROWB);
    const uint32_t b_lane = (uint32_t)(((lane & 7) + ((lane >> 4) & 1) * 8) * ROWB +
                                       ((lane >> 3) & 1) * 16) +
                            (uint32_t)(warp_n * 64 * ROWB);
    const uint32_t bH = sb + SM_B0 + b_lane;
    const uint32_t bL = sb + SM_B0 + TILEB + b_lane;

    float b0[8], b1[8], cv0[8], cv1[8];
#pragma unroll
    for (int nt = 0; nt < 8; nt++) {
        int col = warp_n * 64 + nt * 8 + (lane & 3) * 2;
        b0[nt] = __ldg(bias + col);
        b1[nt] = __ldg(bias + col + 1);
        if (SCV) {
            cv0[nt] = __ldg(cvec + col);
            cv1[nt] = __ldg(cvec + col + 1);
        }
    }

    stage_B(sb + SM_B0, Bh, Bl, tid);
    int tile = blockIdx.x;
    if (tile < NTILES) stage_A_split(sb + SM_AH, Ah, Al, tile * 128, tid);
    cp_commit();
    cp_wait_all();
    __syncthreads();

    int buf = 0;
    for (; tile < NTILES; tile += PGRID) {
        const int m0 = tile * 128;
        const int nxt = tile + PGRID;
        if (nxt < NTILES)
            stage_A_split(sb + (buf ? SM_AH : SM_B1), Ah, Al, nxt * 128, tid);
        cp_commit();

        float acc[2][8][4];
        ACC_ZERO(acc);
        const uint32_t aB = sb + (buf ? SM_B1 : SM_AH);
        mma_chunk(acc, aB + a_lane, aB + TILEB + a_lane, bH, bL);

#pragma unroll
        for (int mi = 0; mi < 2; mi++) {
            int r0 = m0 + warp_m * 32 + mi * 16 + (lane >> 2);
#pragma unroll
            for (int half = 0; half < 2; half++) {
                int r = r0 + half * 8;
                if (r >= NN) continue;
                const float* rrow = RESID ? (R + (size_t)r * 128) : nullptr;
                float sv = SCV ? __ldg(sev + r) : 0.0f;
#pragma unroll
                for (int nt = 0; nt < 8; nt++) {
                    int col = warp_n * 64 + nt * 8 + (lane & 3) * 2;
                    float x0 = acc[mi][nt][half * 2 + 0] + b0[nt];
                    float x1 = acc[mi][nt][half * 2 + 1] + b1[nt];
                    if (SCV) { x0 = fmaf(sv, cv0[nt], x0); x1 = fmaf(sv, cv1[nt], x1); }
                    float2 rr;
                    if (RESID) rr = *(const float2*)(rrow + col);
                    if (RESID == 2) { x0 += rr.x; x1 += rr.y; }
                    if (GELU) { x0 = gelu_f(x0); x1 = gelu_f(x1); }
                    if (RESID == 1) { x0 += rr.x; x1 += rr.y; }
                    if (WF32)
                        *(float2*)(OutF + (size_t)r * 128 + col) = make_float2(x0, x1);
                    if (WSPLIT) {
                        __nv_bfloat16 h0, l0, h1, l1;
                        split_bf16(x0, h0, l0);
                        split_bf16(x1, h1, l1);
                        *(__nv_bfloat162*)(OutH + (size_t)r * 128 + col) =
                            __nv_bfloat162(h0, h1);
                        *(__nv_bfloat162*)(OutL + (size_t)r * 128 + col) =
                            __nv_bfloat162(l0, l1);
                    }
                }
            }
        }
        cp_wait_all();
        __syncthreads();
        buf ^= 1;
    }
}

// ---------------------------------------------------------------------------
// Combined weights (fp32, exact):
//   Wnb = Wn @ W1b, bnb = bn @ W1b
//   Wsg = Ws @ W1a, bsg = bs @ W1a + bg1
// ---------------------------------------------------------------------------
__global__ void k_wcomb(const float* __restrict__ nw, const float* __restrict__ sw,
                        const float* __restrict__ gw1) {
    int idx = blockIdx.x * blockDim.x + threadIdx.x;
    if (idx >= 4 * 16384) return;
    int which = idx >> 15;            // 0 = Wnb, 1 = Wsg
    int sub = idx & 32767;
    int l = sub >> 14;
    int k = (sub >> 7) & 127;
    int n = sub & 127;
    const float* a;
    const float* b;
    if (which == 0) {
        a = nw + (size_t)l * 16384 + k * 128;
        b = gw1 + (size_t)l * 32768 + 16384 + n;   // W1b (aggr half)
    } else {
        a = sw + (size_t)l * 16384 + k * 128;
        b = gw1 + (size_t)l * 32768 + n;           // W1a (self half)
    }
    float s = 0.0f;
#pragma unroll 8
    for (int m = 0; m < 128; m++) s = fmaf(a[m], b[(size_t)m * 128], s);
    if (which == 0) g_wnb[sub] = s;
    else            g_wsg[sub] = s;
}
__global__ void k_bcomb(const float* __restrict__ nbw, const float* __restrict__ sb,
                        const float* __restrict__ gb1, const float* __restrict__ gw1) {
    int idx = blockIdx.x * blockDim.x + threadIdx.x;
    if (idx >= 4 * CC) return;
    int which = idx >> 8;             // 0 = bnb, 1 = bsg
    int l = (idx >> 7) & 1, n = idx & 127;
    float s = 0.0f;
    if (which == 0) {
#pragma unroll 8
        for (int m = 0; m < 128; m++)
            s = fmaf(nbw[l * 128 + m],
                     gw1[(size_t)l * 32768 + 16384 + (size_t)m * 128 + n], s);
        g_bnb[l * CC + n] = s;
    } else {
#pragma unroll 8
        for (int m = 0; m < 128; m++)
            s = fmaf(sb[l * 128 + m], gw1[(size_t)l * 32768 + (size_t)m * 128 + n], s);
        g_bsg[l * CC + n] = s + gb1[l * 128 + n];
    }
}

// ---------------------------------------------------------------------------
// Weight conversion: fp32 W[K,N] -> bf16 hi/lo B[N,K]
// slots: 0=lift2; per layer: 1+3l=Wsg, 2+3l=Wnb, 3+3l=gate2
// ---------------------------------------------------------------------------
__global__ void wconv_kernel(const float* __restrict__ lw2,
                             const float* __restrict__ gw2) {
    int idx = blockIdx.x * blockDim.x + threadIdx.x;
    if (idx >= WSLOTS * 16384) return;
    int slot = idx >> 14;
    int within = idx & 16383;
    int n = within >> 7;
    int k = within & 127;
    const float* src;
    if (slot == 0) {
        src = lw2 + k * 128 + n;
    } else {
        int l = (slot - 1) / 3, j = (slot - 1) % 3;
        if (j == 0)      src = g_wsg + (size_t)l * 16384 + k * 128 + n;
        else if (j == 1) src = g_wnb + (size_t)l * 16384 + k * 128 + n;
        else             src = gw2 + (size_t)l * 16384 + k * 128 + n;
    }
    __nv_bfloat16 hi, lo;
    split_bf16(*src, hi, lo);
    g_wbh[idx] = hi;
    g_wbl[idx] = lo;
}

// ---------------------------------------------------------------------------
// CSR build
// ---------------------------------------------------------------------------
__global__ void k_zero_cnt() {
    int i = blockIdx.x * blockDim.x + threadIdx.x;
    if (i < NN) g_cnt[i] = 0;
}
__global__ void k_count(const int* __restrict__ ei) {
    int e = blockIdx.x * blockDim.x + threadIdx.x;
    if (e < EE) atomicAdd(&g_cnt[ei[e]], 1);
}
__global__ void k_blocksum() {
    __shared__ int sh[256];
    int i = blockIdx.x * 256 + threadIdx.x;
    int v = (i < NN) ? g_cnt[i] : 0;
    sh[threadIdx.x] = v;
    __syncthreads();
    for (int s = 128; s; s >>= 1) {
        if (threadIdx.x < s) sh[threadIdx.x] += sh[threadIdx.x + s];
        __syncthreads();
    }
    if (threadIdx.x == 0) g_bsum[blockIdx.x] = sh[0];
}
__global__ void k_scan_bsum() {
    __shared__ int sh[512];
    int t = threadIdx.x;
    sh[t] = (t < SCAN_BLOCKS) ? g_bsum[t] : 0;
    __syncthreads();
    for (int off = 1; off < 512; off <<= 1) {
        int v = (t >= off) ? sh[t - off] : 0;
        __syncthreads();
        sh[t] += v;
        __syncthreads();
    }
    if (t < SCAN_BLOCKS) g_boff[t] = sh[t] - g_bsum[t];
}
__global__ void k_rowstart() {
    __shared__ int sh[256];
    int i = blockIdx.x * 256 + threadIdx.x;
    int v = (i < NN) ? g_cnt[i] : 0;
    sh[threadIdx.x] = v;
    __syncthreads();
    for (int off = 1; off < 256; off <<= 1) {
        int u = (threadIdx.x >= off) ? sh[threadIdx.x - off] : 0;
        __syncthreads();
        sh[threadIdx.x] += u;
        __syncthreads();
    }
    if (i < NN) {
        int excl = sh[threadIdx.x] - v + g_boff[blockIdx.x];
        g_rowstart[i] = excl;
        g_cursor[i] = excl;
        if (i == NN - 1) g_rowstart[NN] = excl + v;
    }
}
__global__ void k_fill(const int* __restrict__ ei, const float* __restrict__ ev) {
    int e = blockIdx.x * blockDim.x + threadIdx.x;
    if (e >= EE) return;
    int row = ei[e];
    int pos = atomicAdd(&g_cursor[row], 1);
    g_ecol[pos] = ei[EE + e];
    g_eval[pos] = ev[e];
}

// ---------------------------------------------------------------------------
// Pull aggregation of h: gh[r] = sum ev*h[col] (split); sev[r] = sum ev.
// ---------------------------------------------------------------------------
__global__ void k_aggr() {
    int r = blockIdx.x * 8 + (threadIdx.x >> 5);
    if (r >= NN) return;
    int lane = threadIdx.x & 31;
    int s = g_rowstart[r];
    int e = g_rowstart[r + 1];
    float acc[4] = {0.f, 0.f, 0.f, 0.f};
    float sev = 0.f;
    for (int j = s; j < e; j++) {
        int c = __ldg(&g_ecol[j]);
        float v = __ldg(&g_eval[j]);
        sev += v;
        const float* srow = g_h + (size_t)c * CC + lane;
        acc[0] = fmaf(__ldg(srow),      v, acc[0]);
        acc[1] = fmaf(__ldg(srow + 32), v, acc[1]);
        acc[2] = fmaf(__ldg(srow + 64), v, acc[2]);
        acc[3] = fmaf(__ldg(srow + 96), v, acc[3]);
    }
#pragma unroll
    for (int i = 0; i < 4; i++) {
        __nv_bfloat16 hi, lo;
        split_bf16(acc[i], hi, lo);
        g_agh[(size_t)r * CC + lane + i * 32] = hi;
        g_agl[(size_t)r * CC + lane + i * 32] = lo;
    }
    if (lane == 0) g_sev[r] = sev;
}

// ---------------------------------------------------------------------------
// Lift stage 1 + LayerNorm
// ---------------------------------------------------------------------------
__global__ void lift_hidden_kernel(const float* __restrict__ x,
                                   const float* __restrict__ w1,
                                   const float* __restrict__ b1) {
    int idx = blockIdx.x * blockDim.x + threadIdx.x;
    if (idx >= NN * CC) return;
    int n = idx >> 7;
    int c = idx & 127;
    const float* xr = x + (size_t)n * 9 + 3;
    float acc = b1[c];
#pragma unroll
    for (int i = 0; i < 6; i++)
        acc = fmaf(xr[i], w1[i * CC + c], acc);
    float v = gelu_f(acc);
    __nv_bfloat16 hi, lo;
    split_bf16(v, hi, lo);
    g_uh[idx] = hi;
    g_ul[idx] = lo;
}

__global__ void ln_kernel(const float* __restrict__ h,
                          const float* __restrict__ g,
                          const float* __restrict__ b,
                          float* __restrict__ out) {
    int n = blockIdx.x * 8 + (threadIdx.x >> 5);
    if (n >= NN) return;
    int lane = threadIdx.x & 31;
    const float* r = h + (size_t)n * CC;
    float v[4];
    float s = 0.f;
#pragma unroll
    for (int i = 0; i < 4; i++) { v[i] = r[lane + i * 32]; s += v[i]; }
#pragma unroll
    for (int o = 16; o; o >>= 1) s += __shfl_xor_sync(0xffffffffu, s, o);
    float mu = s * (1.f / 128.f);
    float q = 0.f;
#pragma unroll
    for (int i = 0; i < 4; i++) { float d = v[i] - mu; q = fmaf(d, d, q); }
#pragma unroll
    for (int o = 16; o; o >>= 1) q += __shfl_xor_sync(0xffffffffu, q, o);
    float inv = rsqrtf(q * (1.f / 128.f) + 1e-5f);
#pragma unroll
    for (int i = 0; i < 4; i++) {
        int c = lane + i * 32;
        out[(size_t)n * CC + c] = fmaf((v[i] - mu) * inv, g[c], b[c]);
    }
}

// ---------------------------------------------------------------------------
extern "C" void kernel_launch(void* const* d_in, const int* in_sizes, int n_in,
                              void* d_out, int out_size) {
    const float* x   = (const float*)d_in[0];
    const int*   ei  = (const int*)d_in[1];
    const float* ev  = (const float*)d_in[2];
    const float* lw1 = (const float*)d_in[3];
    const float* lb1 = (const float*)d_in[4];
    const float* lw2 = (const float*)d_in[5];
    const float* lb2 = (const float*)d_in[6];
    const float* sw  = (const float*)d_in[7];
    const float* sb  = (const float*)d_in[8];
    const float* nw  = (const float*)d_in[9];
    const float* nbw = (const float*)d_in[10];
    const float* gw1 = (const float*)d_in[11];
    const float* gb1 = (const float*)d_in[12];
    const float* gw2 = (const float*)d_in[13];
    const float* gb2 = (const float*)d_in[14];
    const float* ng  = (const float*)d_in[15];
    const float* nbt = (const float*)d_in[16];
    float* out = (float*)d_out;

    float *h, *tmp, *zero, *sev, *bnb, *bsg;
    cudaGetSymbolAddress((void**)&h, g_h);
    cudaGetSymbolAddress((void**)&tmp, g_tmp);
    cudaGetSymbolAddress((void**)&zero, g_zero);
    cudaGetSymbolAddress((void**)&sev, g_sev);
    cudaGetSymbolAddress((void**)&bnb, g_bnb);
    cudaGetSymbolAddress((void**)&bsg, g_bsg);
    __nv_bfloat16 *wbh, *wbl, *uh, *ul, *hh, *hl, *agh, *agl;
    cudaGetSymbolAddress((void**)&wbh, g_wbh);
    cudaGetSymbolAddress((void**)&wbl, g_wbl);
    cudaGetSymbolAddress((void**)&uh, g_uh);
    cudaGetSymbolAddress((void**)&ul, g_ul);
    cudaGetSymbolAddress((void**)&hh, g_hh);
    cudaGetSymbolAddress((void**)&hl, g_hl);
    cudaGetSymbolAddress((void**)&agh, g_agh);
    cudaGetSymbolAddress((void**)&agl, g_agl);

    cudaFuncSetAttribute(gemm_pers<0, 0, 1, 1, 0>, cudaFuncAttributeMaxDynamicSharedMemorySize, SM_TOTAL);
    cudaFuncSetAttribute(gemm_pers<0, 0, 1, 0, 0>, cudaFuncAttributeMaxDynamicSharedMemorySize, SM_TOTAL);
    cudaFuncSetAttribute(gemm_pers<1, 2, 0, 1, 1>, cudaFuncAttributeMaxDynamicSharedMemorySize, SM_TOTAL);
    cudaFuncSetAttribute(gemm_pers<0, 1, 1, 1, 0>, cudaFuncAttributeMaxDynamicSharedMemorySize, SM_TOTAL);

    // Combined weights, splits, CSR (once per launch)
    k_wcomb<<<(4 * 16384 + 255) / 256, 256>>>(nw, sw, gw1);
    k_bcomb<<<2, 256>>>(nbw, sb, gb1, gw1);
    wconv_kernel<<<(WSLOTS * 16384 + 255) / 256, 256>>>(lw2, gw2);
    k_zero_cnt<<<SCAN_BLOCKS, 256>>>();
    k_count<<<(EE + 255) / 256, 256>>>(ei);
    k_blocksum<<<SCAN_BLOCKS, 256>>>();
    k_scan_bsum<<<1, 512>>>();
    k_rowstart<<<SCAN_BLOCKS, 256>>>();
    k_fill<<<(EE + 255) / 256, 256>>>(ei, ev);

    // Lift: h (fp32 + split)
    lift_hidden_kernel<<<(NN * CC + 255) / 256, 256>>>(x, lw1, lb1);
    gemm_pers<0, 0, 1, 1, 0><<<PGRID, 256, SM_TOTAL>>>(uh, ul, wbh, wbl, lb2,
                                                       nullptr, nullptr, nullptr,
                                                       h, hh, hl);

    for (int l = 0; l < 2; l++) {
        const __nv_bfloat16* wsgh = wbh + (size_t)(1 + 3 * l) * 16384;
        const __nv_bfloat16* wsgl = wbl + (size_t)(1 + 3 * l) * 16384;
        const __nv_bfloat16* wnbh = wbh + (size_t)(2 + 3 * l) * 16384;
        const __nv_bfloat16* wnbl = wbl + (size_t)(2 + 3 * l) * 16384;
        const __nv_bfloat16* g2h  = wbh + (size_t)(3 + 3 * l) * 16384;
        const __nv_bfloat16* g2l  = wbl + (size_t)(3 + 3 * l) * 16384;

        // gh (split) + sev = pull-gather of h
        k_aggr<<<(NN + 7) / 8, 256>>>();
        // tmp = h @ Wsg + bsg  (fp32)
        gemm_pers<0, 0, 1, 0, 0><<<PGRID, 256, SM_TOTAL>>>(hh, hl, wsgh, wsgl,
                                                           bsg + l * CC, nullptr,
                                                           nullptr, nullptr,
                                                           tmp, nullptr, nullptr);
        // u = gelu(gh@Wnb + tmp + sev*bnb)  (split)
        gemm_pers<1, 2, 0, 1, 1><<<PGRID, 256, SM_TOTAL>>>(agh, agl, wnbh, wnbl,
                                                           zero, tmp, sev,
                                                           bnb + l * CC,
                                                           nullptr, uh, ul);
        // h = h + u @ Wg2 + bg2  (fp32 + split)
        gemm_pers<0, 1, 1, 1, 0><<<PGRID, 256, SM_TOTAL>>>(uh, ul, g2h, g2l,
                                                           gb2 + l * CC, h,
                                                           nullptr, nullptr,
                                                           h, hh, hl);
    }

    ln_kernel<<<(NN + 7) / 8, 256>>>(h, ng, nbt, out);
}